// round 6
// baseline (speedup 1.0000x reference)
#include <cuda_runtime.h>
#include <cuda_bf16.h>
#include <float.h>
#include <math.h>
#include <cstdint>

// ---------------- problem constants ----------------
#define FEAT 1024
#define HID 256
#define MAXN 100000
#define KS 8   // K_SAMPLE

// ---------------- scratch (device globals; no allocation) ----------------
__device__ float g_x[(size_t)MAXN * HID];       // relu(h @ Wfc^T + b)
__device__ float g_spart[2 * (size_t)MAXN];     // partial attention scores (2 col-blocks)
__device__ float g_pmax[256];
__device__ float g_mZ[2];
__device__ float g_pool_part[256 * HID];
__device__ float g_psum[256];
__device__ float g_M[HID];
__device__ int   g_topidx[2 * KS];

// ---------------- helpers ----------------
// split fp32 pair into bf16 hi-pair and lo-pair (packed u32, low element = smaller k)
__device__ __forceinline__ void split_pack2(float v0, float v1, uint32_t& h, uint32_t& l) {
    uint32_t hu;
    asm("cvt.rn.bf16x2.f32 %0, %1, %2;" : "=r"(hu) : "f"(v1), "f"(v0));
    float h0 = __uint_as_float(hu << 16);
    float h1 = __uint_as_float(hu & 0xFFFF0000u);
    float r0 = v0 - h0, r1 = v1 - h1;
    uint32_t lu;
    asm("cvt.rn.bf16x2.f32 %0, %1, %2;" : "=r"(lu) : "f"(r1), "f"(r0));
    h = hu; l = lu;
}

// m16n8k16 row.col bf16 MMA, fp32 accumulate (sm_80+, no 'a' features)
__device__ __forceinline__ void mma_bf16(float* c, uint32_t a0, uint32_t a1,
                                         uint32_t a2, uint32_t a3,
                                         uint32_t b0, uint32_t b1) {
    asm volatile(
        "mma.sync.aligned.m16n8k16.row.col.f32.bf16.bf16.f32 "
        "{%0,%1,%2,%3}, {%4,%5,%6,%7}, {%8,%9}, {%0,%1,%2,%3};\n"
        : "+f"(c[0]), "+f"(c[1]), "+f"(c[2]), "+f"(c[3])
        : "r"(a0), "r"(a1), "r"(a2), "r"(a3), "r"(b0), "r"(b1));
}

__device__ __forceinline__ float load_score(const float* __restrict__ p, int i) {
    return p[i] + p[MAXN + i];
}

// smem record layout: per row (192B stride), per k16-step s (64B), per t (16B):
//   {hi(pair p), hi(pair p+4), lo(pair p), lo(pair p+4)},  p = 8s+t, pair = k/2
// 192B stride => LDS.128 phases (8 threads over 2 rows x 4 t) cover all 32 banks.
#define ROWSTRIDE 192
#define A_ROWS 128
#define B_ROWS 256
#define A_TILE_B (A_ROWS * ROWSTRIDE)        // 24576
#define B_TILE_B (B_ROWS * ROWSTRIDE)        // 49152
#define STAGE_B  (A_TILE_B + B_TILE_B)       // 73728
#define SMEM_TOT (2 * STAGE_B)               // 147456

// ================= bf16-split mma.sync GEMM =================
// CTA tile 128 x 256, BK=32, 8 warps of 64x64.
// EPI=0: (GEMM1) out[row*256 + col] = relu(C + bias[col]); B rows r -> B0[r]
// EPI=1: (GEMM2) cb=blockIdx.y; B rows: r<128 -> Wa[cb*128+r], else Wb[cb*128+r-128]
//        epilogue: partial attn score over 128 channels -> out[cb*MAXN + row]
template <int EPI>
__global__ void __launch_bounds__(256, 1)
gemm_mma(const float* __restrict__ A, const float* __restrict__ B0,
         const float* __restrict__ B1, const float* __restrict__ bias,
         const float* __restrict__ ba, const float* __restrict__ bb,
         const float* __restrict__ Wc,
         float* __restrict__ out, int M, int K)
{
    extern __shared__ __align__(16) char smem[];
    const int tid = threadIdx.x;
    const int lane = tid & 31;
    const int wid = tid >> 5;
    const int wm = wid & 1;         // 2 row-slices of 64
    const int wn = wid >> 1;        // 4 col-slices of 64
    const int g = lane >> 2;        // 0..7
    const int tq = lane & 3;        // 0..3
    const int cb = (EPI == 1) ? blockIdx.y : 0;
    const int rowbase = blockIdx.x * 128;
    const int NIT = K >> 5;

    float acc[4][8][4];
#pragma unroll
    for (int mt = 0; mt < 4; mt++)
#pragma unroll
        for (int nt = 0; nt < 8; nt++)
#pragma unroll
            for (int j = 0; j < 4; j++) acc[mt][nt][j] = 0.f;

    // record decode for this thread (same for all q batches)
    const int rr = tid >> 3;              // base row 0..31 (plus q*32)
    const int ss = (tid >> 2) & 1;
    const int tt = tid & 3;

    // ---- copy one 32-row batch of A (q: 0..3) global->smem directly ----
    auto copy_a = [&](int it, int stage, int q) {
        const int kf = (it << 5) + 16 * ss + 2 * tt;
        const int r = q * 32 + rr;
        char* As = smem + stage * STAGE_B;
        float2 u, v;
        int grow = rowbase + r;
        if (grow < M) {
            const float* src = A + (size_t)grow * K + kf;
            u = *(const float2*)(src);
            v = *(const float2*)(src + 8);
        } else {
            u = make_float2(0.f, 0.f); v = u;
        }
        uint32_t h0, l0, h1, l1;
        split_pack2(u.x, u.y, h0, l0);
        split_pack2(v.x, v.y, h1, l1);
        *(uint4*)(As + r * ROWSTRIDE + ss * 64 + tt * 16) = make_uint4(h0, h1, l0, l1);
    };
    // ---- copy one 32-row batch of B (q: 0..7) ----
    auto copy_b = [&](int it, int stage, int q) {
        const int kf = (it << 5) + 16 * ss + 2 * tt;
        const int r = q * 32 + rr;        // 0..255
        char* Bs = smem + stage * STAGE_B + A_TILE_B;
        const float* brow;
        if (EPI == 0) {
            brow = B0 + (size_t)r * K;
        } else {
            int c = cb * 128 + (r & 127);
            brow = ((r < 128) ? B0 : B1) + (size_t)c * K;
        }
        float2 u = *(const float2*)(brow + kf);
        float2 v = *(const float2*)(brow + kf + 8);
        uint32_t h0, l0, h1, l1;
        split_pack2(u.x, u.y, h0, l0);
        split_pack2(v.x, v.y, h1, l1);
        *(uint4*)(Bs + r * ROWSTRIDE + ss * 64 + tt * 16) = make_uint4(h0, h1, l0, l1);
    };
    auto copy_iter = [&](int it, int stage) {
#pragma unroll
        for (int q = 0; q < 4; q++) copy_a(it, stage, q);
#pragma unroll
        for (int q = 0; q < 8; q++) copy_b(it, stage, q);
    };

    copy_iter(0, 0);
    __syncthreads();

#pragma unroll 1
    for (int it = 0; it < NIT; it++) {
        char* As = smem + (it & 1) * STAGE_B;
        char* Bs = As + A_TILE_B;
#pragma unroll
        for (int s = 0; s < 2; s++) {
            uint4 af[4][2];
#pragma unroll
            for (int mt = 0; mt < 4; mt++) {
                int r0 = wm * 64 + mt * 16 + g;
                af[mt][0] = *(const uint4*)(As + r0 * ROWSTRIDE + s * 64 + tq * 16);
                af[mt][1] = *(const uint4*)(As + (r0 + 8) * ROWSTRIDE + s * 64 + tq * 16);
            }
#pragma unroll
            for (int nt = 0; nt < 8; nt++) {
                int nr = wn * 64 + nt * 8 + g;
                uint4 bf = *(const uint4*)(Bs + nr * ROWSTRIDE + s * 64 + tq * 16);
#pragma unroll
                for (int mt = 0; mt < 4; mt++) {
                    // af[mt][0]={a0h,a2h,a0l,a2l}  af[mt][1]={a1h,a3h,a1l,a3l}
                    // bf = {b0h,b1h,b0l,b1l}
                    mma_bf16(acc[mt][nt], af[mt][0].x, af[mt][1].x, af[mt][0].y, af[mt][1].y, bf.x, bf.y);
                    mma_bf16(acc[mt][nt], af[mt][0].x, af[mt][1].x, af[mt][0].y, af[mt][1].y, bf.z, bf.w);
                    mma_bf16(acc[mt][nt], af[mt][0].z, af[mt][1].z, af[mt][0].w, af[mt][1].w, bf.x, bf.y);
                }
            }
        }

        if (it + 1 < NIT) copy_iter(it + 1, (it + 1) & 1);
        __syncthreads();
    }

    if (EPI == 0) {
#pragma unroll
        for (int mt = 0; mt < 4; mt++) {
            int gr = rowbase + wm * 64 + mt * 16 + g;
#pragma unroll
            for (int nt = 0; nt < 8; nt++) {
                int col = wn * 64 + nt * 8 + tq * 2;
                float b0v = __ldg(&bias[col]);
                float b1v = __ldg(&bias[col + 1]);
                if (gr < M) {
                    float2 v = make_float2(fmaxf(acc[mt][nt][0] + b0v, 0.f),
                                           fmaxf(acc[mt][nt][1] + b1v, 0.f));
                    *(float2*)(out + (size_t)gr * 256 + col) = v;
                }
                if (gr + 8 < M) {
                    float2 v = make_float2(fmaxf(acc[mt][nt][2] + b0v, 0.f),
                                           fmaxf(acc[mt][nt][3] + b1v, 0.f));
                    *(float2*)(out + (size_t)(gr + 8) * 256 + col) = v;
                }
            }
        }
    } else {
        // stash 128x256 tile to smem (stride 261 words: conflict-free column reads)
        float* Sc = (float*)smem;
        const int SCS = 261;
#pragma unroll
        for (int mt = 0; mt < 4; mt++) {
            int lr = wm * 64 + mt * 16 + g;
#pragma unroll
            for (int nt = 0; nt < 8; nt++) {
                int lc = wn * 64 + nt * 8 + tq * 2;
                Sc[lr * SCS + lc]           = acc[mt][nt][0];
                Sc[lr * SCS + lc + 1]       = acc[mt][nt][1];
                Sc[(lr + 8) * SCS + lc]     = acc[mt][nt][2];
                Sc[(lr + 8) * SCS + lc + 1] = acc[mt][nt][3];
            }
        }
        __syncthreads();
        if (tid < 128) {
            int r = tid;
            float sum = 0.f;
#pragma unroll 4
            for (int c = 0; c < 128; c++) {
                float va = Sc[r * SCS + c] + __ldg(&ba[cb * 128 + c]);
                float vb = Sc[r * SCS + 128 + c] + __ldg(&bb[cb * 128 + c]);
                float tv = tanhf(va);
                float gv = 1.0f / (1.0f + __expf(-vb));
                sum = fmaf(tv * gv, __ldg(&Wc[cb * 128 + c]), sum);
            }
            int gr = rowbase + r;
            if (gr < M) out[(size_t)cb * MAXN + gr] = sum;
        }
    }
}

// ---------------- reductions (over composed scores) ----------------
__global__ void reduce_max_k(const float* __restrict__ sp, int N, float* __restrict__ pmax)
{
    __shared__ float sm[256];
    int chunk = (N + gridDim.x - 1) / gridDim.x;
    int start = blockIdx.x * chunk;
    int end = min(start + chunk, N);
    float m = -FLT_MAX;
    for (int i = start + threadIdx.x; i < end; i += blockDim.x)
        m = fmaxf(m, load_score(sp, i));
    sm[threadIdx.x] = m;
    __syncthreads();
    for (int str = 128; str > 0; str >>= 1) {
        if (threadIdx.x < str) sm[threadIdx.x] = fmaxf(sm[threadIdx.x], sm[threadIdx.x + str]);
        __syncthreads();
    }
    if (threadIdx.x == 0) pmax[blockIdx.x] = sm[0];
}

__global__ void finalize_max_k(const float* __restrict__ pmax, float* __restrict__ mZ)
{
    __shared__ float sm[256];
    sm[threadIdx.x] = pmax[threadIdx.x];
    __syncthreads();
    for (int str = 128; str > 0; str >>= 1) {
        if (threadIdx.x < str) sm[threadIdx.x] = fmaxf(sm[threadIdx.x], sm[threadIdx.x + str]);
        __syncthreads();
    }
    if (threadIdx.x == 0) mZ[0] = sm[0];
}

__global__ void pool_partial_k(const float* __restrict__ x, const float* __restrict__ sp,
                               const float* __restrict__ mZ, int N,
                               float* __restrict__ part, float* __restrict__ psum)
{
    const float m = mZ[0];
    int chunk = (N + gridDim.x - 1) / gridDim.x;
    int start = blockIdx.x * chunk;
    int end = min(start + chunk, N);
    int j = threadIdx.x;  // 256 = HID
    float acc = 0.0f, wsum = 0.0f;
    for (int i = start; i < end; i++) {
        float w = __expf(load_score(sp, i) - m);
        acc = fmaf(w, x[(size_t)i * HID + j], acc);
        wsum += w;
    }
    part[blockIdx.x * HID + j] = acc;
    if (j == 0) psum[blockIdx.x] = wsum;
}

__global__ void pool_final_k(const float* __restrict__ part, const float* __restrict__ psum,
                             float* __restrict__ Mout)
{
    __shared__ float sz[256];
    int j = threadIdx.x;
    float acc = 0.0f;
    for (int b = 0; b < 256; b++) acc += part[b * HID + j];
    sz[j] = psum[j];
    __syncthreads();
    for (int str = 128; str > 0; str >>= 1) {
        if (j < str) sz[j] += sz[j + str];
        __syncthreads();
    }
    Mout[j] = acc / sz[0];
}

// ---------------- top-8 / bottom-8 selection ----
__global__ void topk_kernel(const float* __restrict__ sp, int N, int* __restrict__ out_idx)
{
    const int tid = threadIdx.x;
    float tv[KS], bv[KS];
    int ti[KS], bi[KS];
#pragma unroll
    for (int k = 0; k < KS; k++) { tv[k] = -FLT_MAX; ti[k] = 0; bv[k] = FLT_MAX; bi[k] = 0; }

    for (int i = tid; i < N; i += 256) {
        float v = load_score(sp, i);
        if (v > tv[KS - 1]) {
            tv[KS - 1] = v; ti[KS - 1] = i;
            for (int j = KS - 1; j > 0; j--) {
                if (tv[j] > tv[j - 1]) {
                    float fv = tv[j]; tv[j] = tv[j - 1]; tv[j - 1] = fv;
                    int fi = ti[j]; ti[j] = ti[j - 1]; ti[j - 1] = fi;
                } else break;
            }
        }
        if (v < bv[KS - 1]) {
            bv[KS - 1] = v; bi[KS - 1] = i;
            for (int j = KS - 1; j > 0; j--) {
                if (bv[j] < bv[j - 1]) {
                    float fv = bv[j]; bv[j] = bv[j - 1]; bv[j - 1] = fv;
                    int fi = bi[j]; bi[j] = bi[j - 1]; bi[j - 1] = fi;
                } else break;
            }
        }
    }

    __shared__ float cv[256 * KS];
    __shared__ int   ci[256 * KS];
    __shared__ float rv[256];
    __shared__ int   rs[256];

#pragma unroll
    for (int k = 0; k < KS; k++) { cv[tid * KS + k] = tv[k]; ci[tid * KS + k] = ti[k]; }
    __syncthreads();
    for (int pass = 0; pass < KS; pass++) {
        float bestv = -FLT_MAX; int bestslot = tid * KS;
#pragma unroll
        for (int k = 0; k < KS; k++) {
            int sl = tid * KS + k;
            if (cv[sl] > bestv) { bestv = cv[sl]; bestslot = sl; }
        }
        rv[tid] = bestv; rs[tid] = bestslot;
        __syncthreads();
        for (int str = 128; str > 0; str >>= 1) {
            if (tid < str && rv[tid + str] > rv[tid]) { rv[tid] = rv[tid + str]; rs[tid] = rs[tid + str]; }
            __syncthreads();
        }
        if (tid == 0) { out_idx[pass] = ci[rs[0]]; cv[rs[0]] = -FLT_MAX; }
        __syncthreads();
    }

#pragma unroll
    for (int k = 0; k < KS; k++) { cv[tid * KS + k] = bv[k]; ci[tid * KS + k] = bi[k]; }
    __syncthreads();
    for (int pass = 0; pass < KS; pass++) {
        float bestv = FLT_MAX; int bestslot = tid * KS;
#pragma unroll
        for (int k = 0; k < KS; k++) {
            int sl = tid * KS + k;
            if (cv[sl] < bestv) { bestv = cv[sl]; bestslot = sl; }
        }
        rv[tid] = bestv; rs[tid] = bestslot;
        __syncthreads();
        for (int str = 128; str > 0; str >>= 1) {
            if (tid < str && rv[tid + str] < rv[tid]) { rv[tid] = rv[tid + str]; rs[tid] = rs[tid + str]; }
            __syncthreads();
        }
        if (tid == 0) { out_idx[KS + pass] = ci[rs[0]]; cv[rs[0]] = FLT_MAX; }
        __syncthreads();
    }
}

// ---------------- final tiny kernel ----------------
__global__ void final_kernel(const float* __restrict__ Mv,
                             const float* __restrict__ W_cls, const float* __restrict__ b_cls,
                             const float* __restrict__ W_inst, const float* __restrict__ b_inst,
                             const int* __restrict__ label_p,
                             const float* __restrict__ xbuf, const int* __restrict__ top_idx,
                             float* __restrict__ out)
{
    int lane = threadIdx.x;  // 32 threads
    int label = label_p[0];
    float my = 0.0f;
    if (lane < 2 * KS) {
        int id = top_idx[lane];
        const float* xr = xbuf + (size_t)id * HID;
        const float* w0 = W_inst + (size_t)(label * 2 + 0) * HID;
        const float* w1 = W_inst + (size_t)(label * 2 + 1) * HID;
        float s0 = b_inst[label * 2 + 0], s1 = b_inst[label * 2 + 1];
        for (int j = 0; j < HID; j++) {
            float xv = xr[j];
            s0 = fmaf(xv, w0[j], s0);
            s1 = fmaf(xv, w1[j], s1);
        }
        int t = (lane < KS) ? 1 : 0;
        float a0 = s0 + ((t == 0) ? 0.0f : 1.0f);
        float a1 = s1 + ((t == 1) ? 0.0f : 1.0f);
        float mm = fmaxf(a0, a1);
        float lse = mm + logf(expf(a0 - mm) + expf(a1 - mm));
        float sy = (t == 1) ? s1 : s0;
        my = lse - sy;
    }
#pragma unroll
    for (int off = 16; off >= 1; off >>= 1)
        my += __shfl_xor_sync(0xffffffffu, my, off);

    if (lane == 0) {
        float loss = my / (float)(2 * KS);
        float l0 = b_cls[0], l1 = b_cls[1];
        for (int j = 0; j < HID; j++) {
            float m = Mv[j];
            l0 = fmaf(W_cls[j], m, l0);
            l1 = fmaf(W_cls[HID + j], m, l1);
        }
        float mm = fmaxf(l0, l1);
        float e0 = expf(l0 - mm), e1 = expf(l1 - mm);
        float Z = e0 + e1;
        out[0] = l0;
        out[1] = l1;
        out[2] = e0 / Z;
        out[3] = e1 / Z;
        out[4] = (l1 > l0) ? 1.0f : 0.0f;
        out[5] = loss;
    }
}

// ---------------- launch ----------------
extern "C" void kernel_launch(void* const* d_in, const int* in_sizes, int n_in,
                              void* d_out, int out_size)
{
    const float* h     = (const float*)d_in[0];
    const int*   label = (const int*)d_in[1];
    const float* W_fc  = (const float*)d_in[2];
    const float* b_fc  = (const float*)d_in[3];
    const float* Wa    = (const float*)d_in[4];
    const float* ba    = (const float*)d_in[5];
    const float* Wb    = (const float*)d_in[6];
    const float* bb    = (const float*)d_in[7];
    const float* Wc    = (const float*)d_in[8];
    const float* bc    = (const float*)d_in[9];  // softmax-invariant; unused downstream
    const float* W_cls = (const float*)d_in[10];
    const float* b_cls = (const float*)d_in[11];
    const float* W_inst= (const float*)d_in[12];
    const float* b_inst= (const float*)d_in[13];
    (void)bc;

    int N = in_sizes[0] / FEAT;

    float *px, *pspart, *ppmax, *pmZ, *ppart, *ppsum, *pM;
    int *ptop;
    cudaGetSymbolAddress((void**)&px, g_x);
    cudaGetSymbolAddress((void**)&pspart, g_spart);
    cudaGetSymbolAddress((void**)&ppmax, g_pmax);
    cudaGetSymbolAddress((void**)&pmZ, g_mZ);
    cudaGetSymbolAddress((void**)&ppart, g_pool_part);
    cudaGetSymbolAddress((void**)&ppsum, g_psum);
    cudaGetSymbolAddress((void**)&pM, g_M);
    cudaGetSymbolAddress((void**)&ptop, g_topidx);

    int rbs = (N + 127) / 128;

    // K1: x = relu(h @ Wfc^T + b_fc); CTA 128x256, one col-block
    cudaFuncSetAttribute(gemm_mma<0>, cudaFuncAttributeMaxDynamicSharedMemorySize, SMEM_TOT);
    gemm_mma<0><<<dim3(rbs, 1), 256, SMEM_TOT>>>(
        h, W_fc, nullptr, b_fc, nullptr, nullptr, nullptr, px, N, FEAT);

    // K2: partial attention scores; 2 col-blocks of 128 attention channels
    cudaFuncSetAttribute(gemm_mma<1>, cudaFuncAttributeMaxDynamicSharedMemorySize, SMEM_TOT);
    gemm_mma<1><<<dim3(rbs, 2), 256, SMEM_TOT>>>(
        px, Wa, Wb, nullptr, ba, bb, Wc, pspart, N, HID);

    reduce_max_k<<<256, 256>>>(pspart, N, ppmax);
    finalize_max_k<<<1, 256>>>(ppmax, pmZ);
    pool_partial_k<<<256, 256>>>(px, pspart, pmZ, N, ppart, ppsum);
    pool_final_k<<<1, 256>>>(ppart, ppsum, pM);
    topk_kernel<<<1, 256>>>(pspart, N, ptop);
    final_kernel<<<1, 32>>>(pM, W_cls, b_cls, W_inst, b_inst, label, px, ptop,
                            (float*)d_out);
}

// round 9
// speedup vs baseline: 1.9029x; 1.9029x over previous
#include <cuda_runtime.h>
#include <cuda_bf16.h>
#include <float.h>
#include <math.h>
#include <cstdint>

// ---------------- problem constants ----------------
#define FEAT 1024
#define HID 256
#define MAXN 100000
#define KS 8   // K_SAMPLE

// ---------------- scratch (device globals; no allocation) ----------------
__device__ float g_x[(size_t)MAXN * HID];       // relu(h @ Wfc^T + b)
__device__ float g_spart[2 * (size_t)MAXN];     // partial attention scores (2 planes)
__device__ float g_pool_part[256 * HID];
__device__ float g_psum[256];
__device__ float g_cand_v[256 * 16];            // per block: 8 top vals, 8 bottom vals
__device__ int   g_cand_i[256 * 16];

// ---------------- helpers ----------------
// split fp32 pair into bf16 hi-pair and lo-pair (packed u32, low element = smaller k)
__device__ __forceinline__ void split_pack2(float v0, float v1, uint32_t& h, uint32_t& l) {
    uint32_t hu;
    asm("cvt.rn.bf16x2.f32 %0, %1, %2;" : "=r"(hu) : "f"(v1), "f"(v0));
    float h0 = __uint_as_float(hu << 16);
    float h1 = __uint_as_float(hu & 0xFFFF0000u);
    float r0 = v0 - h0, r1 = v1 - h1;
    uint32_t lu;
    asm("cvt.rn.bf16x2.f32 %0, %1, %2;" : "=r"(lu) : "f"(r1), "f"(r0));
    h = hu; l = lu;
}

// m16n8k16 row.col bf16 MMA, fp32 accumulate (sm_80+, no 'a' features)
__device__ __forceinline__ void mma_bf16(float* c, uint32_t a0, uint32_t a1,
                                         uint32_t a2, uint32_t a3,
                                         uint32_t b0, uint32_t b1) {
    asm volatile(
        "mma.sync.aligned.m16n8k16.row.col.f32.bf16.bf16.f32 "
        "{%0,%1,%2,%3}, {%4,%5,%6,%7}, {%8,%9}, {%0,%1,%2,%3};\n"
        : "+f"(c[0]), "+f"(c[1]), "+f"(c[2]), "+f"(c[3])
        : "r"(a0), "r"(a1), "r"(a2), "r"(a3), "r"(b0), "r"(b1));
}

__device__ __forceinline__ float load_score(const float* __restrict__ p, int i) {
    return p[i] + p[MAXN + i];
}

// smem record layout: per row (192B stride), per k16-step s (64B), per t (16B):
//   {hi(pair p), hi(pair p+4), lo(pair p), lo(pair p+4)},  p = 8s+t, pair = k/2
#define ROWSTRIDE 192
#define A_ROWS 128
#define B_ROWS 256
#define A_TILE_B (A_ROWS * ROWSTRIDE)        // 24576
#define B_TILE_B (B_ROWS * ROWSTRIDE)        // 49152
#define STAGE_B  (A_TILE_B + B_TILE_B)       // 73728
#define SMEM_TOT (2 * STAGE_B)               // 147456

// ================= bf16-split mma.sync GEMM =================
// CTA tile 128 x 256, BK=32, 8 warps of 64x64, register-prefetch pipeline.
// EPI=0: out[row*256 + col] = relu(C + bias[col]); B rows r -> B0[r]
// EPI=1: cb=blockIdx.y; B rows: r<128 -> Wa[cb*128+r], else Wb[cb*128+r-128]
//        epilogue: partial attn score over 128 channels -> out[cb*MAXN + row]
template <int EPI>
__global__ void __launch_bounds__(256)
gemm_mma(const float* __restrict__ A, const float* __restrict__ B0,
         const float* __restrict__ B1, const float* __restrict__ bias,
         const float* __restrict__ ba, const float* __restrict__ bb,
         const float* __restrict__ Wc,
         float* __restrict__ out, int M, int K)
{
    extern __shared__ __align__(16) char smem[];
    const int tid = threadIdx.x;
    const int lane = tid & 31;
    const int wid = tid >> 5;
    const int wm = wid & 1;         // 2 row-slices of 64
    const int wn = wid >> 1;        // 4 col-slices of 64
    const int g = lane >> 2;        // 0..7
    const int tq = lane & 3;        // 0..3
    const int cb = (EPI == 1) ? blockIdx.y : 0;
    const int rowbase = blockIdx.x * 128;
    const int NIT = K >> 5;
    const int rr = tid >> 3;        // record row within 32-batch
    const int ss = (tid >> 2) & 1;
    const int tt = tid & 3;

    float acc[4][8][4];
#pragma unroll
    for (int mt = 0; mt < 4; mt++)
#pragma unroll
        for (int nt = 0; nt < 8; nt++)
#pragma unroll
            for (int j = 0; j < 4; j++) acc[mt][nt][j] = 0.f;

    auto ld_a = [&](int it, int q, float4& d) {
        int kf = (it << 5) + 16 * ss + 2 * tt;
        int r = q * 32 + rr;
        int grow = rowbase + r;
        if (grow < M) {
            const float* src = A + (size_t)grow * K + kf;
            float2 u = *(const float2*)(src);
            float2 v = *(const float2*)(src + 8);
            d = make_float4(u.x, u.y, v.x, v.y);
        } else d = make_float4(0.f, 0.f, 0.f, 0.f);
    };
    auto ld_b = [&](int it, int q, float4& d) {
        int kf = (it << 5) + 16 * ss + 2 * tt;
        int r = q * 32 + rr;
        const float* brow;
        if (EPI == 0) brow = B0 + (size_t)r * K;
        else { int c = cb * 128 + (r & 127); brow = ((r < 128) ? B0 : B1) + (size_t)c * K; }
        float2 u = *(const float2*)(brow + kf);
        float2 v = *(const float2*)(brow + kf + 8);
        d = make_float4(u.x, u.y, v.x, v.y);
    };
    auto st_a = [&](int stage, int q, const float4& d) {
        char* As = smem + stage * STAGE_B;
        int r = q * 32 + rr;
        uint32_t h0, l0, h1, l1;
        split_pack2(d.x, d.y, h0, l0);
        split_pack2(d.z, d.w, h1, l1);
        *(uint4*)(As + r * ROWSTRIDE + ss * 64 + tt * 16) = make_uint4(h0, h1, l0, l1);
    };
    auto st_b = [&](int stage, int q, const float4& d) {
        char* Bs = smem + stage * STAGE_B + A_TILE_B;
        int r = q * 32 + rr;
        uint32_t h0, l0, h1, l1;
        split_pack2(d.x, d.y, h0, l0);
        split_pack2(d.z, d.w, h1, l1);
        *(uint4*)(Bs + r * ROWSTRIDE + ss * 64 + tt * 16) = make_uint4(h0, h1, l0, l1);
    };
    auto compute_s = [&](const char* As, const char* Bs, int s) {
        uint4 af[4][2];
#pragma unroll
        for (int mt = 0; mt < 4; mt++) {
            int r0 = wm * 64 + mt * 16 + g;
            af[mt][0] = *(const uint4*)(As + r0 * ROWSTRIDE + s * 64 + tq * 16);
            af[mt][1] = *(const uint4*)(As + (r0 + 8) * ROWSTRIDE + s * 64 + tq * 16);
        }
#pragma unroll
        for (int nt = 0; nt < 8; nt++) {
            int nr = wn * 64 + nt * 8 + g;
            uint4 bf = *(const uint4*)(Bs + nr * ROWSTRIDE + s * 64 + tq * 16);
#pragma unroll
            for (int mt = 0; mt < 4; mt++) {
                // af[mt][0]={a0h,a2h,a0l,a2l}  af[mt][1]={a1h,a3h,a1l,a3l}
                // bf = {b0h,b1h,b0l,b1l}
                mma_bf16(acc[mt][nt], af[mt][0].x, af[mt][1].x, af[mt][0].y, af[mt][1].y, bf.x, bf.y);
                mma_bf16(acc[mt][nt], af[mt][0].x, af[mt][1].x, af[mt][0].y, af[mt][1].y, bf.z, bf.w);
                mma_bf16(acc[mt][nt], af[mt][0].z, af[mt][1].z, af[mt][0].w, af[mt][1].w, bf.x, bf.y);
            }
        }
    };

    // prologue: stage 0
    {
        float4 d;
#pragma unroll
        for (int q = 0; q < 4; q++) { ld_a(0, q, d); st_a(0, q, d); }
#pragma unroll
        for (int q = 0; q < 8; q++) { ld_b(0, q, d); st_b(0, q, d); }
    }
    __syncthreads();

#pragma unroll 1
    for (int it = 0; it < NIT; it++) {
        const char* As = smem + (it & 1) * STAGE_B;
        const char* Bs = As + A_TILE_B;
        const int nst = (it + 1) & 1;
        const bool pf = (it + 1 < NIT);
        float4 s0, s1, s2, s3, s4, s5;

        // half1 prefetch: A records + first 2 B records
        if (pf) {
            ld_a(it + 1, 0, s0); ld_a(it + 1, 1, s1);
            ld_a(it + 1, 2, s2); ld_a(it + 1, 3, s3);
            ld_b(it + 1, 0, s4); ld_b(it + 1, 1, s5);
        }
        compute_s(As, Bs, 0);
        if (pf) {
            st_a(nst, 0, s0); st_a(nst, 1, s1); st_a(nst, 2, s2); st_a(nst, 3, s3);
            st_b(nst, 0, s4); st_b(nst, 1, s5);
            // half2 prefetch: remaining 6 B records
            ld_b(it + 1, 2, s0); ld_b(it + 1, 3, s1); ld_b(it + 1, 4, s2);
            ld_b(it + 1, 5, s3); ld_b(it + 1, 6, s4); ld_b(it + 1, 7, s5);
        }
        compute_s(As, Bs, 1);
        if (pf) {
            st_b(nst, 2, s0); st_b(nst, 3, s1); st_b(nst, 4, s2);
            st_b(nst, 5, s3); st_b(nst, 6, s4); st_b(nst, 7, s5);
        }
        __syncthreads();
    }

    if (EPI == 0) {
#pragma unroll
        for (int mt = 0; mt < 4; mt++) {
            int gr = rowbase + wm * 64 + mt * 16 + g;
#pragma unroll
            for (int nt = 0; nt < 8; nt++) {
                int col = wn * 64 + nt * 8 + tq * 2;
                float b0v = __ldg(&bias[col]);
                float b1v = __ldg(&bias[col + 1]);
                if (gr < M) {
                    float2 v = make_float2(fmaxf(acc[mt][nt][0] + b0v, 0.f),
                                           fmaxf(acc[mt][nt][1] + b1v, 0.f));
                    *(float2*)(out + (size_t)gr * 256 + col) = v;
                }
                if (gr + 8 < M) {
                    float2 v = make_float2(fmaxf(acc[mt][nt][2] + b0v, 0.f),
                                           fmaxf(acc[mt][nt][3] + b1v, 0.f));
                    *(float2*)(out + (size_t)(gr + 8) * 256 + col) = v;
                }
            }
        }
    } else {
        // stash 128x256 tile to smem (row stride 261 words), then per-row score
        float* Sc = (float*)smem;
        const int SCS = 261;
#pragma unroll
        for (int mt = 0; mt < 4; mt++) {
            int lr = wm * 64 + mt * 16 + g;
#pragma unroll
            for (int nt = 0; nt < 8; nt++) {
                int lc = wn * 64 + nt * 8 + tq * 2;
                Sc[lr * SCS + lc]           = acc[mt][nt][0];
                Sc[lr * SCS + lc + 1]       = acc[mt][nt][1];
                Sc[(lr + 8) * SCS + lc]     = acc[mt][nt][2];
                Sc[(lr + 8) * SCS + lc + 1] = acc[mt][nt][3];
            }
        }
        __syncthreads();
        if (tid < 128) {
            int r = tid;
            float sum = 0.f;
#pragma unroll 4
            for (int c = 0; c < 128; c++) {
                float va = Sc[r * SCS + c] + __ldg(&ba[cb * 128 + c]);
                float vb = Sc[r * SCS + 128 + c] + __ldg(&bb[cb * 128 + c]);
                float tv = tanhf(va);
                float gv = 1.0f / (1.0f + __expf(-vb));
                sum = fmaf(tv * gv, __ldg(&Wc[cb * 128 + c]), sum);
            }
            int gr = rowbase + r;
            if (gr < M) out[(size_t)cb * MAXN + gr] = sum;
        }
    }
}

// ============ fused pooling partials + per-block top/bottom-8 ==============
// w = exp(s) (no max subtraction; scores bounded by |Wc|_1 ~ 2)
__global__ void pool_topk_partial(const float* __restrict__ x,
                                  const float* __restrict__ sp, int N,
                                  float* __restrict__ part, float* __restrict__ psum,
                                  float* __restrict__ cand_v, int* __restrict__ cand_i)
{
    __shared__ float ws[256];
    __shared__ float cv[256 * KS];
    __shared__ int   ci[256 * KS];
    __shared__ float rv[256];
    __shared__ int   rs[256];

    const int tid = threadIdx.x;
    int chunk = (N + gridDim.x - 1) / gridDim.x;
    int start = blockIdx.x * chunk;
    int end = min(start + chunk, N);

    float tv[KS], bv[KS];
    int ti[KS], bi[KS];
#pragma unroll
    for (int k = 0; k < KS; k++) { tv[k] = -FLT_MAX; ti[k] = 0; bv[k] = FLT_MAX; bi[k] = 0; }

    float accx = 0.f, wsum = 0.f;
    for (int t0 = start; t0 < end; t0 += 256) {
        int i = t0 + tid;
        float w = 0.f;
        if (i < end) {
            float s = load_score(sp, i);
            w = __expf(s);
            // maintain this thread's top/bottom-8 over its strided subset
            if (s > tv[KS - 1]) {
                tv[KS - 1] = s; ti[KS - 1] = i;
                for (int j = KS - 1; j > 0; j--) {
                    if (tv[j] > tv[j - 1]) {
                        float fv = tv[j]; tv[j] = tv[j - 1]; tv[j - 1] = fv;
                        int fi = ti[j]; ti[j] = ti[j - 1]; ti[j - 1] = fi;
                    } else break;
                }
            }
            if (s < bv[KS - 1]) {
                bv[KS - 1] = s; bi[KS - 1] = i;
                for (int j = KS - 1; j > 0; j--) {
                    if (bv[j] < bv[j - 1]) {
                        float fv = bv[j]; bv[j] = bv[j - 1]; bv[j - 1] = fv;
                        int fi = bi[j]; bi[j] = bi[j - 1]; bi[j - 1] = fi;
                    } else break;
                }
            }
        }
        ws[tid] = w;
        __syncthreads();
        int cnt = min(256, end - t0);
        for (int ii = 0; ii < cnt; ii++) {
            float w2 = ws[ii];
            accx = fmaf(w2, x[(size_t)(t0 + ii) * HID + tid], accx);
            wsum += w2;
        }
        __syncthreads();
    }
    part[blockIdx.x * HID + tid] = accx;
    if (tid == 0) psum[blockIdx.x] = wsum;

    // ---- block-level top 8 ----
#pragma unroll
    for (int k = 0; k < KS; k++) { cv[tid * KS + k] = tv[k]; ci[tid * KS + k] = ti[k]; }
    __syncthreads();
    for (int pass = 0; pass < KS; pass++) {
        float bestv = -FLT_MAX; int bestslot = tid * KS;
#pragma unroll
        for (int k = 0; k < KS; k++) {
            int sl = tid * KS + k;
            if (cv[sl] > bestv) { bestv = cv[sl]; bestslot = sl; }
        }
        rv[tid] = bestv; rs[tid] = bestslot;
        __syncthreads();
        for (int str = 128; str > 0; str >>= 1) {
            if (tid < str && rv[tid + str] > rv[tid]) { rv[tid] = rv[tid + str]; rs[tid] = rs[tid + str]; }
            __syncthreads();
        }
        if (tid == 0) {
            cand_v[blockIdx.x * 16 + pass] = rv[0];
            cand_i[blockIdx.x * 16 + pass] = ci[rs[0]];
            cv[rs[0]] = -FLT_MAX;
        }
        __syncthreads();
    }
    // ---- block-level bottom 8 ----
#pragma unroll
    for (int k = 0; k < KS; k++) { cv[tid * KS + k] = bv[k]; ci[tid * KS + k] = bi[k]; }
    __syncthreads();
    for (int pass = 0; pass < KS; pass++) {
        float bestv = FLT_MAX; int bestslot = tid * KS;
#pragma unroll
        for (int k = 0; k < KS; k++) {
            int sl = tid * KS + k;
            if (cv[sl] < bestv) { bestv = cv[sl]; bestslot = sl; }
        }
        rv[tid] = bestv; rs[tid] = bestslot;
        __syncthreads();
        for (int str = 128; str > 0; str >>= 1) {
            if (tid < str && rv[tid + str] < rv[tid]) { rv[tid] = rv[tid + str]; rs[tid] = rs[tid + str]; }
            __syncthreads();
        }
        if (tid == 0) {
            cand_v[blockIdx.x * 16 + KS + pass] = rv[0];
            cand_i[blockIdx.x * 16 + KS + pass] = ci[rs[0]];
            cv[rs[0]] = FLT_MAX;
        }
        __syncthreads();
    }
}

// ======= fused final: candidate merge + pool merge + losses + output =======
__global__ void final_fused(const float* __restrict__ cand_v, const int* __restrict__ cand_i,
                            const float* __restrict__ part, const float* __restrict__ psum,
                            const float* __restrict__ W_cls, const float* __restrict__ b_cls,
                            const float* __restrict__ W_inst, const float* __restrict__ b_inst,
                            const int* __restrict__ label_p, const float* __restrict__ xbuf,
                            float* __restrict__ out)
{
    __shared__ float cv[256 * KS];
    __shared__ int   ci[256 * KS];
    __shared__ float rv[256];
    __shared__ int   rs[256];
    __shared__ float Msh[HID];
    __shared__ float szs[256];
    __shared__ int   sel[2 * KS];
    const int tid = threadIdx.x;

    // ---- global top 8 (slot 0..7 of each block) ----
#pragma unroll
    for (int k = 0; k < KS; k++) {
        cv[tid * KS + k] = cand_v[tid * 16 + k];
        ci[tid * KS + k] = cand_i[tid * 16 + k];
    }
    __syncthreads();
    for (int pass = 0; pass < KS; pass++) {
        float bestv = -FLT_MAX; int bestslot = tid * KS;
#pragma unroll
        for (int k = 0; k < KS; k++) {
            int sl = tid * KS + k;
            if (cv[sl] > bestv) { bestv = cv[sl]; bestslot = sl; }
        }
        rv[tid] = bestv; rs[tid] = bestslot;
        __syncthreads();
        for (int str = 128; str > 0; str >>= 1) {
            if (tid < str && rv[tid + str] > rv[tid]) { rv[tid] = rv[tid + str]; rs[tid] = rs[tid + str]; }
            __syncthreads();
        }
        if (tid == 0) { sel[pass] = ci[rs[0]]; cv[rs[0]] = -FLT_MAX; }
        __syncthreads();
    }
    // ---- global bottom 8 (slot 8..15 of each block) ----
#pragma unroll
    for (int k = 0; k < KS; k++) {
        cv[tid * KS + k] = cand_v[tid * 16 + KS + k];
        ci[tid * KS + k] = cand_i[tid * 16 + KS + k];
    }
    __syncthreads();
    for (int pass = 0; pass < KS; pass++) {
        float bestv = FLT_MAX; int bestslot = tid * KS;
#pragma unroll
        for (int k = 0; k < KS; k++) {
            int sl = tid * KS + k;
            if (cv[sl] < bestv) { bestv = cv[sl]; bestslot = sl; }
        }
        rv[tid] = bestv; rs[tid] = bestslot;
        __syncthreads();
        for (int str = 128; str > 0; str >>= 1) {
            if (tid < str && rv[tid + str] < rv[tid]) { rv[tid] = rv[tid + str]; rs[tid] = rs[tid + str]; }
            __syncthreads();
        }
        if (tid == 0) { sel[KS + pass] = ci[rs[0]]; cv[rs[0]] = FLT_MAX; }
        __syncthreads();
    }

    // ---- pool merge: M[j] = sum_b part[b][j] / sum_b psum[b] ----
    float accm = 0.f;
    for (int b = 0; b < 256; b++) accm += part[b * HID + tid];
    szs[tid] = psum[tid];
    __syncthreads();
    for (int str = 128; str > 0; str >>= 1) {
        if (tid < str) szs[tid] += szs[tid + str];
        __syncthreads();
    }
    Msh[tid] = accm / szs[0];
    __syncthreads();

    // ---- warp 0: instance SVM loss + bag classifier ----
    if (tid < 32) {
        int lane = tid;
        int label = label_p[0];
        float my = 0.0f;
        if (lane < 2 * KS) {
            int id = sel[lane];
            const float* xr = xbuf + (size_t)id * HID;
            const float* w0 = W_inst + (size_t)(label * 2 + 0) * HID;
            const float* w1 = W_inst + (size_t)(label * 2 + 1) * HID;
            float s0 = b_inst[label * 2 + 0], s1 = b_inst[label * 2 + 1];
            for (int j = 0; j < HID; j++) {
                float xv = xr[j];
                s0 = fmaf(xv, w0[j], s0);
                s1 = fmaf(xv, w1[j], s1);
            }
            int t = (lane < KS) ? 1 : 0;
            float a0 = s0 + ((t == 0) ? 0.0f : 1.0f);
            float a1 = s1 + ((t == 1) ? 0.0f : 1.0f);
            float mm = fmaxf(a0, a1);
            float lse = mm + logf(expf(a0 - mm) + expf(a1 - mm));
            float sy = (t == 1) ? s1 : s0;
            my = lse - sy;
        }
#pragma unroll
        for (int off = 16; off >= 1; off >>= 1)
            my += __shfl_xor_sync(0xffffffffu, my, off);

        if (lane == 0) {
            float loss = my / (float)(2 * KS);
            float l0 = b_cls[0], l1 = b_cls[1];
            for (int j = 0; j < HID; j++) {
                float m = Msh[j];
                l0 = fmaf(W_cls[j], m, l0);
                l1 = fmaf(W_cls[HID + j], m, l1);
            }
            float mm = fmaxf(l0, l1);
            float e0 = expf(l0 - mm), e1 = expf(l1 - mm);
            float Z = e0 + e1;
            out[0] = l0;
            out[1] = l1;
            out[2] = e0 / Z;
            out[3] = e1 / Z;
            out[4] = (l1 > l0) ? 1.0f : 0.0f;
            out[5] = loss;
        }
    }
}

// ---------------- launch ----------------
extern "C" void kernel_launch(void* const* d_in, const int* in_sizes, int n_in,
                              void* d_out, int out_size)
{
    const float* h     = (const float*)d_in[0];
    const int*   label = (const int*)d_in[1];
    const float* W_fc  = (const float*)d_in[2];
    const float* b_fc  = (const float*)d_in[3];
    const float* Wa    = (const float*)d_in[4];
    const float* ba    = (const float*)d_in[5];
    const float* Wb    = (const float*)d_in[6];
    const float* bb    = (const float*)d_in[7];
    const float* Wc    = (const float*)d_in[8];
    const float* bc    = (const float*)d_in[9];  // softmax-invariant; unused downstream
    const float* W_cls = (const float*)d_in[10];
    const float* b_cls = (const float*)d_in[11];
    const float* W_inst= (const float*)d_in[12];
    const float* b_inst= (const float*)d_in[13];
    (void)bc;

    int N = in_sizes[0] / FEAT;

    float *px, *pspart, *ppart, *ppsum, *pcv;
    int *pci;
    cudaGetSymbolAddress((void**)&px, g_x);
    cudaGetSymbolAddress((void**)&pspart, g_spart);
    cudaGetSymbolAddress((void**)&ppart, g_pool_part);
    cudaGetSymbolAddress((void**)&ppsum, g_psum);
    cudaGetSymbolAddress((void**)&pcv, g_cand_v);
    cudaGetSymbolAddress((void**)&pci, g_cand_i);

    int rbs = (N + 127) / 128;

    // K1: x = relu(h @ Wfc^T + b_fc); CTA 128x256
    cudaFuncSetAttribute(gemm_mma<0>, cudaFuncAttributeMaxDynamicSharedMemorySize, SMEM_TOT);
    gemm_mma<0><<<dim3(rbs, 1), 256, SMEM_TOT>>>(
        h, W_fc, nullptr, b_fc, nullptr, nullptr, nullptr, px, N, FEAT);

    // K2: partial attention scores; 2 col-blocks of 128 attention channels
    cudaFuncSetAttribute(gemm_mma<1>, cudaFuncAttributeMaxDynamicSharedMemorySize, SMEM_TOT);
    gemm_mma<1><<<dim3(rbs, 2), 256, SMEM_TOT>>>(
        px, Wa, Wb, nullptr, ba, bb, Wc, pspart, N, HID);

    // fused pooling partials + per-block top/bottom-8 candidates
    pool_topk_partial<<<256, 256>>>(px, pspart, N, ppart, ppsum, pcv, pci);

    // fused final: merge candidates + pool + instance loss + bag classifier
    final_fused<<<1, 256>>>(pcv, pci, ppart, ppsum, W_cls, b_cls,
                            W_inst, b_inst, label, px, (float*)d_out);
}

// round 11
// speedup vs baseline: 2.3182x; 1.2183x over previous
#include <cuda_runtime.h>
#include <cuda_fp16.h>
#include <float.h>
#include <math.h>
#include <cstdint>

// ---------------- problem constants ----------------
#define FEAT 1024
#define HID 256
#define MAXN 100000
#define KS 8   // K_SAMPLE

// ---------------- scratch (device globals; no allocation) ----------------
__device__ float g_x[(size_t)MAXN * HID];       // relu(h @ Wfc^T + b)
__device__ float g_spart[2 * (size_t)MAXN];     // partial attention scores (2 planes)
__device__ float g_pool_part[256 * HID];
__device__ float g_psum[256];
__device__ float g_cand_v[256 * 16];            // per block: 8 top vals, 8 bottom vals
__device__ int   g_cand_i[256 * 16];

// ---------------- helpers ----------------
// pack two fp32 into fp16x2 (v0 -> low half)
__device__ __forceinline__ uint32_t pack_f16(float v0, float v1) {
    __half2 p = __floats2half2_rn(v0, v1);
    return *reinterpret_cast<uint32_t*>(&p);
}
// split fp32 pair into fp16 hi-pair and fp16 lo-pair (residual)
__device__ __forceinline__ void split_f16(float v0, float v1, uint32_t& h, uint32_t& l) {
    __half h0 = __float2half_rn(v0), h1 = __float2half_rn(v1);
    float r0 = v0 - __half2float(h0);
    float r1 = v1 - __half2float(h1);
    __half2 hp = __halves2half2(h0, h1);
    __half2 lp = __floats2half2_rn(r0, r1);
    h = *reinterpret_cast<uint32_t*>(&hp);
    l = *reinterpret_cast<uint32_t*>(&lp);
}

// m16n8k16 row.col fp16 MMA, fp32 accumulate (sm_80+, no 'a' features)
__device__ __forceinline__ void mma_f16(float* c, uint32_t a0, uint32_t a1,
                                        uint32_t a2, uint32_t a3,
                                        uint32_t b0, uint32_t b1) {
    asm volatile(
        "mma.sync.aligned.m16n8k16.row.col.f32.f16.f16.f32 "
        "{%0,%1,%2,%3}, {%4,%5,%6,%7}, {%8,%9}, {%0,%1,%2,%3};\n"
        : "+f"(c[0]), "+f"(c[1]), "+f"(c[2]), "+f"(c[3])
        : "r"(a0), "r"(a1), "r"(a2), "r"(a3), "r"(b0), "r"(b1));
}

__device__ __forceinline__ float load_score(const float* __restrict__ p, int i) {
    return p[i] + p[MAXN + i];
}

// ---- smem layout ----
// A (single fp16): per row 96B stride (64B data): per k16-step s (32B), per t (8B):
//   {a(pair p), a(pair p+4)},  p = 8s+t, pair = k/2.
//   LDS.64 fragment phases: addr mod 128 = 96g + 8tq -> 16 distinct over 16 lanes.
// B (fp16 hi+lo): per row 192B stride (128B data): per s (64B), per t (16B):
//   {hi(p), hi(p+4), lo(p), lo(p+4)}.
//   LDS.128 phases: 64g + 16tq mod 128 -> conflict-free (even g {0..48}, odd {64..112}).
#define RS_A 96
#define RS_B 192
#define A_ROWS 128
#define B_ROWS 256
#define A_TILE_B (A_ROWS * RS_A)             // 12288
#define B_TILE_B (B_ROWS * RS_B)             // 49152
#define STAGE_B  (A_TILE_B + B_TILE_B)       // 61440
#define SMEM_TOT (2 * STAGE_B)               // 122880
#define EPI_SMEM (128 * 261 * 4)             // 133632 (EPI=1 scratch)

// ================= fp16 2-term mma.sync GEMM =================
// CTA tile 128 x 256, BK=32, 8 warps of 64x64, register-prefetch pipeline.
// C = A_fp16 @ (B_hi + B_lo)^T  (error = resid(A)*B ~ 2^-12 relative)
// EPI=0: out[row*256 + col] = relu(C + bias[col]); B rows r -> B0[r]
// EPI=1: cb=blockIdx.y; B rows: r<128 -> Wa[cb*128+r], else Wb[cb*128+r-128]
//        epilogue: partial attn score over 128 channels -> out[cb*MAXN + row]
template <int EPI>
__global__ void __launch_bounds__(256)
gemm_mma(const float* __restrict__ A, const float* __restrict__ B0,
         const float* __restrict__ B1, const float* __restrict__ bias,
         const float* __restrict__ ba, const float* __restrict__ bb,
         const float* __restrict__ Wc,
         float* __restrict__ out, int M, int K)
{
    extern __shared__ __align__(16) char smem[];
    const int tid = threadIdx.x;
    const int lane = tid & 31;
    const int wid = tid >> 5;
    const int wm = wid & 1;         // 2 row-slices of 64
    const int wn = wid >> 1;        // 4 col-slices of 64
    const int g = lane >> 2;        // 0..7
    const int tq = lane & 3;        // 0..3
    const int cb = (EPI == 1) ? blockIdx.y : 0;
    const int rowbase = blockIdx.x * 128;
    const int NIT = K >> 5;
    const int rr = tid >> 3;        // record row within 32-batch
    const int ss = (tid >> 2) & 1;
    const int tt = tid & 3;

    float acc[4][8][4];
#pragma unroll
    for (int mt = 0; mt < 4; mt++)
#pragma unroll
        for (int nt = 0; nt < 8; nt++)
#pragma unroll
            for (int j = 0; j < 4; j++) acc[mt][nt][j] = 0.f;

    auto ld_a = [&](int it, int q, float4& d) {
        int kf = (it << 5) + 16 * ss + 2 * tt;
        int r = q * 32 + rr;
        int grow = rowbase + r;
        if (grow < M) {
            const float* src = A + (size_t)grow * K + kf;
            float2 u = *(const float2*)(src);
            float2 v = *(const float2*)(src + 8);
            d = make_float4(u.x, u.y, v.x, v.y);
        } else d = make_float4(0.f, 0.f, 0.f, 0.f);
    };
    auto ld_b = [&](int it, int q, float4& d) {
        int kf = (it << 5) + 16 * ss + 2 * tt;
        int r = q * 32 + rr;
        const float* brow;
        if (EPI == 0) brow = B0 + (size_t)r * K;
        else { int c = cb * 128 + (r & 127); brow = ((r < 128) ? B0 : B1) + (size_t)c * K; }
        float2 u = *(const float2*)(brow + kf);
        float2 v = *(const float2*)(brow + kf + 8);
        d = make_float4(u.x, u.y, v.x, v.y);
    };
    auto st_a = [&](int stage, int q, const float4& d) {
        char* As = smem + stage * STAGE_B;
        int r = q * 32 + rr;
        uint32_t p0 = pack_f16(d.x, d.y);
        uint32_t p1 = pack_f16(d.z, d.w);
        *(uint2*)(As + r * RS_A + ss * 32 + tt * 8) = make_uint2(p0, p1);
    };
    auto st_b = [&](int stage, int q, const float4& d) {
        char* Bs = smem + stage * STAGE_B + A_TILE_B;
        int r = q * 32 + rr;
        uint32_t h0, l0, h1, l1;
        split_f16(d.x, d.y, h0, l0);
        split_f16(d.z, d.w, h1, l1);
        *(uint4*)(Bs + r * RS_B + ss * 64 + tt * 16) = make_uint4(h0, h1, l0, l1);
    };
    auto compute_s = [&](const char* As, const char* Bs, int s) {
        uint2 af[4][2];
#pragma unroll
        for (int mt = 0; mt < 4; mt++) {
            int r0 = wm * 64 + mt * 16 + g;
            af[mt][0] = *(const uint2*)(As + r0 * RS_A + s * 32 + tq * 8);
            af[mt][1] = *(const uint2*)(As + (r0 + 8) * RS_A + s * 32 + tq * 8);
        }
#pragma unroll
        for (int nt = 0; nt < 8; nt++) {
            int nr = wn * 64 + nt * 8 + g;
            uint4 bf = *(const uint4*)(Bs + nr * RS_B + s * 64 + tq * 16);
#pragma unroll
            for (int mt = 0; mt < 4; mt++) {
                // af[mt][0]={a0,a2} (row r0), af[mt][1]={a1,a3} (row r0+8)
                // bf = {b0h,b1h,b0l,b1l}
                mma_f16(acc[mt][nt], af[mt][0].x, af[mt][1].x, af[mt][0].y, af[mt][1].y, bf.x, bf.y);
                mma_f16(acc[mt][nt], af[mt][0].x, af[mt][1].x, af[mt][0].y, af[mt][1].y, bf.z, bf.w);
            }
        }
    };

    // prologue: stage 0
    {
        float4 d;
#pragma unroll
        for (int q = 0; q < 4; q++) { ld_a(0, q, d); st_a(0, q, d); }
#pragma unroll
        for (int q = 0; q < 8; q++) { ld_b(0, q, d); st_b(0, q, d); }
    }
    __syncthreads();

#pragma unroll 1
    for (int it = 0; it < NIT; it++) {
        const char* As = smem + (it & 1) * STAGE_B;
        const char* Bs = As + A_TILE_B;
        const int nst = (it + 1) & 1;
        const bool pf = (it + 1 < NIT);
        float4 s0, s1, s2, s3, s4, s5;

        // half1 prefetch: A records + first 2 B records
        if (pf) {
            ld_a(it + 1, 0, s0); ld_a(it + 1, 1, s1);
            ld_a(it + 1, 2, s2); ld_a(it + 1, 3, s3);
            ld_b(it + 1, 0, s4); ld_b(it + 1, 1, s5);
        }
        compute_s(As, Bs, 0);
        if (pf) {
            st_a(nst, 0, s0); st_a(nst, 1, s1); st_a(nst, 2, s2); st_a(nst, 3, s3);
            st_b(nst, 0, s4); st_b(nst, 1, s5);
            // half2 prefetch: remaining 6 B records
            ld_b(it + 1, 2, s0); ld_b(it + 1, 3, s1); ld_b(it + 1, 4, s2);
            ld_b(it + 1, 5, s3); ld_b(it + 1, 6, s4); ld_b(it + 1, 7, s5);
        }
        compute_s(As, Bs, 1);
        if (pf) {
            st_b(nst, 2, s0); st_b(nst, 3, s1); st_b(nst, 4, s2);
            st_b(nst, 5, s3); st_b(nst, 6, s4); st_b(nst, 7, s5);
        }
        __syncthreads();
    }

    if (EPI == 0) {
#pragma unroll
        for (int mt = 0; mt < 4; mt++) {
            int gr = rowbase + wm * 64 + mt * 16 + g;
#pragma unroll
            for (int nt = 0; nt < 8; nt++) {
                int col = wn * 64 + nt * 8 + tq * 2;
                float b0v = __ldg(&bias[col]);
                float b1v = __ldg(&bias[col + 1]);
                if (gr < M) {
                    float2 v = make_float2(fmaxf(acc[mt][nt][0] + b0v, 0.f),
                                           fmaxf(acc[mt][nt][1] + b1v, 0.f));
                    *(float2*)(out + (size_t)gr * 256 + col) = v;
                }
                if (gr + 8 < M) {
                    float2 v = make_float2(fmaxf(acc[mt][nt][2] + b0v, 0.f),
                                           fmaxf(acc[mt][nt][3] + b1v, 0.f));
                    *(float2*)(out + (size_t)(gr + 8) * 256 + col) = v;
                }
            }
        }
    } else {
        // stash 128x256 tile to smem (row stride 261 words), then per-row score
        float* Sc = (float*)smem;
        const int SCS = 261;
#pragma unroll
        for (int mt = 0; mt < 4; mt++) {
            int lr = wm * 64 + mt * 16 + g;
#pragma unroll
            for (int nt = 0; nt < 8; nt++) {
                int lc = wn * 64 + nt * 8 + tq * 2;
                Sc[lr * SCS + lc]           = acc[mt][nt][0];
                Sc[lr * SCS + lc + 1]       = acc[mt][nt][1];
                Sc[(lr + 8) * SCS + lc]     = acc[mt][nt][2];
                Sc[(lr + 8) * SCS + lc + 1] = acc[mt][nt][3];
            }
        }
        __syncthreads();
        if (tid < 128) {
            int r = tid;
            float sum = 0.f;
#pragma unroll 4
            for (int c = 0; c < 128; c++) {
                float va = Sc[r * SCS + c] + __ldg(&ba[cb * 128 + c]);
                float vb = Sc[r * SCS + 128 + c] + __ldg(&bb[cb * 128 + c]);
                float tv = tanhf(va);
                float gv = 1.0f / (1.0f + __expf(-vb));
                sum = fmaf(tv * gv, __ldg(&Wc[cb * 128 + c]), sum);
            }
            int gr = rowbase + r;
            if (gr < M) out[(size_t)cb * MAXN + gr] = sum;
        }
    }
}

// ============ fused pooling partials + per-block top/bottom-8 ==============
// w = exp(s) (no max subtraction; scores bounded by |Wc|_1 ~ 2)
__global__ void pool_topk_partial(const float* __restrict__ x,
                                  const float* __restrict__ sp, int N,
                                  float* __restrict__ part, float* __restrict__ psum,
                                  float* __restrict__ cand_v, int* __restrict__ cand_i)
{
    __shared__ float ws[256];
    __shared__ float cv[256 * KS];
    __shared__ int   ci[256 * KS];
    __shared__ float rv[256];
    __shared__ int   rs[256];

    const int tid = threadIdx.x;
    int chunk = (N + gridDim.x - 1) / gridDim.x;
    int start = blockIdx.x * chunk;
    int end = min(start + chunk, N);

    float tv[KS], bv[KS];
    int ti[KS], bi[KS];
#pragma unroll
    for (int k = 0; k < KS; k++) { tv[k] = -FLT_MAX; ti[k] = 0; bv[k] = FLT_MAX; bi[k] = 0; }

    float accx = 0.f, wsum = 0.f;
    for (int t0 = start; t0 < end; t0 += 256) {
        int i = t0 + tid;
        float w = 0.f;
        if (i < end) {
            float s = load_score(sp, i);
            w = __expf(s);
            if (s > tv[KS - 1]) {
                tv[KS - 1] = s; ti[KS - 1] = i;
                for (int j = KS - 1; j > 0; j--) {
                    if (tv[j] > tv[j - 1]) {
                        float fv = tv[j]; tv[j] = tv[j - 1]; tv[j - 1] = fv;
                        int fi = ti[j]; ti[j] = ti[j - 1]; ti[j - 1] = fi;
                    } else break;
                }
            }
            if (s < bv[KS - 1]) {
                bv[KS - 1] = s; bi[KS - 1] = i;
                for (int j = KS - 1; j > 0; j--) {
                    if (bv[j] < bv[j - 1]) {
                        float fv = bv[j]; bv[j] = bv[j - 1]; bv[j - 1] = fv;
                        int fi = bi[j]; bi[j] = bi[j - 1]; bi[j - 1] = fi;
                    } else break;
                }
            }
        }
        ws[tid] = w;
        __syncthreads();
        int cnt = min(256, end - t0);
        for (int ii = 0; ii < cnt; ii++) {
            float w2 = ws[ii];
            accx = fmaf(w2, x[(size_t)(t0 + ii) * HID + tid], accx);
            wsum += w2;
        }
        __syncthreads();
    }
    part[blockIdx.x * HID + tid] = accx;
    if (tid == 0) psum[blockIdx.x] = wsum;

    // ---- block-level top 8 ----
#pragma unroll
    for (int k = 0; k < KS; k++) { cv[tid * KS + k] = tv[k]; ci[tid * KS + k] = ti[k]; }
    __syncthreads();
    for (int pass = 0; pass < KS; pass++) {
        float bestv = -FLT_MAX; int bestslot = tid * KS;
#pragma unroll
        for (int k = 0; k < KS; k++) {
            int sl = tid * KS + k;
            if (cv[sl] > bestv) { bestv = cv[sl]; bestslot = sl; }
        }
        rv[tid] = bestv; rs[tid] = bestslot;
        __syncthreads();
        for (int str = 128; str > 0; str >>= 1) {
            if (tid < str && rv[tid + str] > rv[tid]) { rv[tid] = rv[tid + str]; rs[tid] = rs[tid + str]; }
            __syncthreads();
        }
        if (tid == 0) {
            cand_v[blockIdx.x * 16 + pass] = rv[0];
            cand_i[blockIdx.x * 16 + pass] = ci[rs[0]];
            cv[rs[0]] = -FLT_MAX;
        }
        __syncthreads();
    }
    // ---- block-level bottom 8 ----
#pragma unroll
    for (int k = 0; k < KS; k++) { cv[tid * KS + k] = bv[k]; ci[tid * KS + k] = bi[k]; }
    __syncthreads();
    for (int pass = 0; pass < KS; pass++) {
        float bestv = FLT_MAX; int bestslot = tid * KS;
#pragma unroll
        for (int k = 0; k < KS; k++) {
            int sl = tid * KS + k;
            if (cv[sl] < bestv) { bestv = cv[sl]; bestslot = sl; }
        }
        rv[tid] = bestv; rs[tid] = bestslot;
        __syncthreads();
        for (int str = 128; str > 0; str >>= 1) {
            if (tid < str && rv[tid + str] < rv[tid]) { rv[tid] = rv[tid + str]; rs[tid] = rs[tid + str]; }
            __syncthreads();
        }
        if (tid == 0) {
            cand_v[blockIdx.x * 16 + KS + pass] = rv[0];
            cand_i[blockIdx.x * 16 + KS + pass] = ci[rs[0]];
            cv[rs[0]] = FLT_MAX;
        }
        __syncthreads();
    }
}

// ======= fused final: candidate merge + pool merge + losses + output =======
__global__ void final_fused(const float* __restrict__ cand_v, const int* __restrict__ cand_i,
                            const float* __restrict__ part, const float* __restrict__ psum,
                            const float* __restrict__ W_cls, const float* __restrict__ b_cls,
                            const float* __restrict__ W_inst, const float* __restrict__ b_inst,
                            const int* __restrict__ label_p, const float* __restrict__ xbuf,
                            float* __restrict__ out)
{
    __shared__ float cv[256 * KS];
    __shared__ int   ci[256 * KS];
    __shared__ float rv[256];
    __shared__ int   rs[256];
    __shared__ float Msh[HID];
    __shared__ float szs[256];
    __shared__ int   sel[2 * KS];
    const int tid = threadIdx.x;

    // ---- global top 8 (slot 0..7 of each block) ----
#pragma unroll
    for (int k = 0; k < KS; k++) {
        cv[tid * KS + k] = cand_v[tid * 16 + k];
        ci[tid * KS + k] = cand_i[tid * 16 + k];
    }
    __syncthreads();
    for (int pass = 0; pass < KS; pass++) {
        float bestv = -FLT_MAX; int bestslot = tid * KS;
#pragma unroll
        for (int k = 0; k < KS; k++) {
            int sl = tid * KS + k;
            if (cv[sl] > bestv) { bestv = cv[sl]; bestslot = sl; }
        }
        rv[tid] = bestv; rs[tid] = bestslot;
        __syncthreads();
        for (int str = 128; str > 0; str >>= 1) {
            if (tid < str && rv[tid + str] > rv[tid]) { rv[tid] = rv[tid + str]; rs[tid] = rs[tid + str]; }
            __syncthreads();
        }
        if (tid == 0) { sel[pass] = ci[rs[0]]; cv[rs[0]] = -FLT_MAX; }
        __syncthreads();
    }
    // ---- global bottom 8 (slot 8..15 of each block) ----
#pragma unroll
    for (int k = 0; k < KS; k++) {
        cv[tid * KS + k] = cand_v[tid * 16 + KS + k];
        ci[tid * KS + k] = cand_i[tid * 16 + KS + k];
    }
    __syncthreads();
    for (int pass = 0; pass < KS; pass++) {
        float bestv = FLT_MAX; int bestslot = tid * KS;
#pragma unroll
        for (int k = 0; k < KS; k++) {
            int sl = tid * KS + k;
            if (cv[sl] < bestv) { bestv = cv[sl]; bestslot = sl; }
        }
        rv[tid] = bestv; rs[tid] = bestslot;
        __syncthreads();
        for (int str = 128; str > 0; str >>= 1) {
            if (tid < str && rv[tid + str] < rv[tid]) { rv[tid] = rv[tid + str]; rs[tid] = rs[tid + str]; }
            __syncthreads();
        }
        if (tid == 0) { sel[KS + pass] = ci[rs[0]]; cv[rs[0]] = FLT_MAX; }
        __syncthreads();
    }

    // ---- pool merge: M[j] = sum_b part[b][j] / sum_b psum[b] ----
    float accm = 0.f;
    for (int b = 0; b < 256; b++) accm += part[b * HID + tid];
    szs[tid] = psum[tid];
    __syncthreads();
    for (int str = 128; str > 0; str >>= 1) {
        if (tid < str) szs[tid] += szs[tid + str];
        __syncthreads();
    }
    Msh[tid] = accm / szs[0];
    __syncthreads();

    // ---- warp 0: instance SVM loss + bag classifier ----
    if (tid < 32) {
        int lane = tid;
        int label = label_p[0];
        float my = 0.0f;
        if (lane < 2 * KS) {
            int id = sel[lane];
            const float* xr = xbuf + (size_t)id * HID;
            const float* w0 = W_inst + (size_t)(label * 2 + 0) * HID;
            const float* w1 = W_inst + (size_t)(label * 2 + 1) * HID;
            float s0 = b_inst[label * 2 + 0], s1 = b_inst[label * 2 + 1];
            for (int j = 0; j < HID; j++) {
                float xv = xr[j];
                s0 = fmaf(xv, w0[j], s0);
                s1 = fmaf(xv, w1[j], s1);
            }
            int t = (lane < KS) ? 1 : 0;
            float a0 = s0 + ((t == 0) ? 0.0f : 1.0f);
            float a1 = s1 + ((t == 1) ? 0.0f : 1.0f);
            float mm = fmaxf(a0, a1);
            float lse = mm + logf(expf(a0 - mm) + expf(a1 - mm));
            float sy = (t == 1) ? s1 : s0;
            my = lse - sy;
        }
#pragma unroll
        for (int off = 16; off >= 1; off >>= 1)
            my += __shfl_xor_sync(0xffffffffu, my, off);

        if (lane == 0) {
            float loss = my / (float)(2 * KS);
            float l0 = b_cls[0], l1 = b_cls[1];
            for (int j = 0; j < HID; j++) {
                float m = Msh[j];
                l0 = fmaf(W_cls[j], m, l0);
                l1 = fmaf(W_cls[HID + j], m, l1);
            }
            float mm = fmaxf(l0, l1);
            float e0 = expf(l0 - mm), e1 = expf(l1 - mm);
            float Z = e0 + e1;
            out[0] = l0;
            out[1] = l1;
            out[2] = e0 / Z;
            out[3] = e1 / Z;
            out[4] = (l1 > l0) ? 1.0f : 0.0f;
            out[5] = loss;
        }
    }
}

// ---------------- launch ----------------
extern "C" void kernel_launch(void* const* d_in, const int* in_sizes, int n_in,
                              void* d_out, int out_size)
{
    const float* h     = (const float*)d_in[0];
    const int*   label = (const int*)d_in[1];
    const float* W_fc  = (const float*)d_in[2];
    const float* b_fc  = (const float*)d_in[3];
    const float* Wa    = (const float*)d_in[4];
    const float* ba    = (const float*)d_in[5];
    const float* Wb    = (const float*)d_in[6];
    const float* bb    = (const float*)d_in[7];
    const float* Wc    = (const float*)d_in[8];
    const float* bc    = (const float*)d_in[9];  // softmax-invariant; unused downstream
    const float* W_cls = (const float*)d_in[10];
    const float* b_cls = (const float*)d_in[11];
    const float* W_inst= (const float*)d_in[12];
    const float* b_inst= (const float*)d_in[13];
    (void)bc;

    int N = in_sizes[0] / FEAT;

    float *px, *pspart, *ppart, *ppsum, *pcv;
    int *pci;
    cudaGetSymbolAddress((void**)&px, g_x);
    cudaGetSymbolAddress((void**)&pspart, g_spart);
    cudaGetSymbolAddress((void**)&ppart, g_pool_part);
    cudaGetSymbolAddress((void**)&ppsum, g_psum);
    cudaGetSymbolAddress((void**)&pcv, g_cand_v);
    cudaGetSymbolAddress((void**)&pci, g_cand_i);

    int rbs = (N + 127) / 128;

    // K1: x = relu(h @ Wfc^T + b_fc); CTA 128x256
    cudaFuncSetAttribute(gemm_mma<0>, cudaFuncAttributeMaxDynamicSharedMemorySize, SMEM_TOT);
    gemm_mma<0><<<dim3(rbs, 1), 256, SMEM_TOT>>>(
        h, W_fc, nullptr, b_fc, nullptr, nullptr, nullptr, px, N, FEAT);

    // K2: partial attention scores; 2 col-blocks of 128 attention channels
    const int SMEM_K2 = (EPI_SMEM > SMEM_TOT) ? EPI_SMEM : SMEM_TOT;
    cudaFuncSetAttribute(gemm_mma<1>, cudaFuncAttributeMaxDynamicSharedMemorySize, SMEM_K2);
    gemm_mma<1><<<dim3(rbs, 2), 256, SMEM_K2>>>(
        px, Wa, Wb, nullptr, ba, bb, Wc, pspart, N, HID);

    // fused pooling partials + per-block top/bottom-8 candidates
    pool_topk_partial<<<256, 256>>>(px, pspart, N, ppart, ppsum, pcv, pci);

    // fused final: merge candidates + pool + instance loss + bag classifier
    final_fused<<<1, 256>>>(pcv, pci, ppart, ppsum, W_cls, b_cls,
                            W_inst, b_inst, label, px, (float*)d_out);
}

// round 12
// speedup vs baseline: 2.4253x; 1.0462x over previous
#include <cuda_runtime.h>
#include <cuda_fp16.h>
#include <float.h>
#include <math.h>
#include <cstdint>

// ---------------- problem constants ----------------
#define FEAT 1024
#define HID 256
#define MAXN 100000
#define KS 8   // K_SAMPLE
#define NB 64  // pool/topk partial blocks

// ---------------- scratch (device globals; no allocation) ----------------
__device__ float g_x[(size_t)MAXN * HID];       // relu(h @ Wfc^T + b)
__device__ float g_spart[2 * (size_t)MAXN];     // partial attention scores (2 planes)
__device__ float g_pool_part[NB * HID];
__device__ float g_psum[NB];
__device__ float g_cand_v[NB * 16];             // per block: 8 top vals, 8 bottom vals
__device__ int   g_cand_i[NB * 16];

// ---------------- helpers ----------------
__device__ __forceinline__ uint32_t pack_f16(float v0, float v1) {
    __half2 p = __floats2half2_rn(v0, v1);
    return *reinterpret_cast<uint32_t*>(&p);
}
__device__ __forceinline__ void split_f16(float v0, float v1, uint32_t& h, uint32_t& l) {
    __half h0 = __float2half_rn(v0), h1 = __float2half_rn(v1);
    float r0 = v0 - __half2float(h0);
    float r1 = v1 - __half2float(h1);
    __half2 hp = __halves2half2(h0, h1);
    __half2 lp = __floats2half2_rn(r0, r1);
    h = *reinterpret_cast<uint32_t*>(&hp);
    l = *reinterpret_cast<uint32_t*>(&lp);
}

// m16n8k16 row.col fp16 MMA, fp32 accumulate (sm_80+, no 'a' features)
__device__ __forceinline__ void mma_f16(float* c, uint32_t a0, uint32_t a1,
                                        uint32_t a2, uint32_t a3,
                                        uint32_t b0, uint32_t b1) {
    asm volatile(
        "mma.sync.aligned.m16n8k16.row.col.f32.f16.f16.f32 "
        "{%0,%1,%2,%3}, {%4,%5,%6,%7}, {%8,%9}, {%0,%1,%2,%3};\n"
        : "+f"(c[0]), "+f"(c[1]), "+f"(c[2]), "+f"(c[3])
        : "r"(a0), "r"(a1), "r"(a2), "r"(a3), "r"(b0), "r"(b1));
}

__device__ __forceinline__ float load_score(const float* __restrict__ p, int i) {
    return p[i] + p[MAXN + i];
}

// ---- smem layout (proven in R11) ----
// A fp16: 96B row stride, per s (32B), per t (8B). LDS.64 phases conflict-free.
// B fp16 hi+lo: 192B row stride, per s (64B), per t (16B). LDS.128 conflict-free.
#define RS_A 96
#define RS_B 192
#define A_ROWS 128
#define B_ROWS 256
#define A_TILE_B (A_ROWS * RS_A)             // 12288
#define B_TILE_B (B_ROWS * RS_B)             // 49152
#define STAGE_B  (A_TILE_B + B_TILE_B)       // 61440
#define SMEM_TOT (2 * STAGE_B)               // 122880
#define SCS 132                              // K2 epi pb-stash row stride (floats)

// ================= fp16 2-term mma.sync GEMM, 512 threads =================
// CTA tile 128 x 256, BK=32, 16 warps of 64x32, register-prefetch pipeline.
// C = A_fp16 @ (B_hi + B_lo)^T
// EPI=0: out[row*256+col] = relu(C + bias[col]); B rows r -> B0[r]
// EPI=1: cb=blockIdx.y; B rows: r<128 -> Wa[cb*128+r] (pa), else Wb[...] (pb)
//        epilogue: partial attn score over 128 channels -> out[cb*MAXN + row]
template <int EPI>
__global__ void __launch_bounds__(512)
gemm_mma(const float* __restrict__ A, const float* __restrict__ B0,
         const float* __restrict__ B1, const float* __restrict__ bias,
         const float* __restrict__ ba, const float* __restrict__ bb,
         const float* __restrict__ Wc,
         float* __restrict__ out, int M, int K)
{
    extern __shared__ __align__(16) char smem[];
    const int tid = threadIdx.x;
    const int lane = tid & 31;
    const int wid = tid >> 5;
    const int wm = wid & 1;         // 2 row-slices of 64
    const int wn = wid >> 1;        // 8 col-slices of 32
    const int g = lane >> 2;        // 0..7
    const int tq = lane & 3;        // 0..3
    const int cb = (EPI == 1) ? blockIdx.y : 0;
    const int rowbase = blockIdx.x * 128;
    const int NIT = K >> 5;
    const int rr = tid >> 3;        // record row within 64-batch (0..63)
    const int ss = (tid >> 2) & 1;
    const int tt = tid & 3;

    float acc[4][4][4];
#pragma unroll
    for (int mt = 0; mt < 4; mt++)
#pragma unroll
        for (int nt = 0; nt < 4; nt++)
#pragma unroll
            for (int j = 0; j < 4; j++) acc[mt][nt][j] = 0.f;

    auto ld_a = [&](int it, int q, float4& d) {        // q: 0..1 (64 rows each)
        int kf = (it << 5) + 16 * ss + 2 * tt;
        int r = q * 64 + rr;
        int grow = rowbase + r;
        if (grow < M) {
            const float* src = A + (size_t)grow * K + kf;
            float2 u = *(const float2*)(src);
            float2 v = *(const float2*)(src + 8);
            d = make_float4(u.x, u.y, v.x, v.y);
        } else d = make_float4(0.f, 0.f, 0.f, 0.f);
    };
    auto ld_b = [&](int it, int q, float4& d) {        // q: 0..3 (64 rows each)
        int kf = (it << 5) + 16 * ss + 2 * tt;
        int r = q * 64 + rr;
        const float* brow;
        if (EPI == 0) brow = B0 + (size_t)r * K;
        else { int c = cb * 128 + (r & 127); brow = ((r < 128) ? B0 : B1) + (size_t)c * K; }
        float2 u = *(const float2*)(brow + kf);
        float2 v = *(const float2*)(brow + kf + 8);
        d = make_float4(u.x, u.y, v.x, v.y);
    };
    auto st_a = [&](int stage, int q, const float4& d) {
        char* As = smem + stage * STAGE_B;
        int r = q * 64 + rr;
        uint32_t p0 = pack_f16(d.x, d.y);
        uint32_t p1 = pack_f16(d.z, d.w);
        *(uint2*)(As + r * RS_A + ss * 32 + tt * 8) = make_uint2(p0, p1);
    };
    auto st_b = [&](int stage, int q, const float4& d) {
        char* Bs = smem + stage * STAGE_B + A_TILE_B;
        int r = q * 64 + rr;
        uint32_t h0, l0, h1, l1;
        split_f16(d.x, d.y, h0, l0);
        split_f16(d.z, d.w, h1, l1);
        *(uint4*)(Bs + r * RS_B + ss * 64 + tt * 16) = make_uint4(h0, h1, l0, l1);
    };
    auto compute_s = [&](const char* As, const char* Bs, int s) {
        uint2 af[4][2];
#pragma unroll
        for (int mt = 0; mt < 4; mt++) {
            int r0 = wm * 64 + mt * 16 + g;
            af[mt][0] = *(const uint2*)(As + r0 * RS_A + s * 32 + tq * 8);
            af[mt][1] = *(const uint2*)(As + (r0 + 8) * RS_A + s * 32 + tq * 8);
        }
#pragma unroll
        for (int nt = 0; nt < 4; nt++) {
            int nr = wn * 32 + nt * 8 + g;
            uint4 bf = *(const uint4*)(Bs + nr * RS_B + s * 64 + tq * 16);
#pragma unroll
            for (int mt = 0; mt < 4; mt++) {
                mma_f16(acc[mt][nt], af[mt][0].x, af[mt][1].x, af[mt][0].y, af[mt][1].y, bf.x, bf.y);
                mma_f16(acc[mt][nt], af[mt][0].x, af[mt][1].x, af[mt][0].y, af[mt][1].y, bf.z, bf.w);
            }
        }
    };

    // prologue: stage 0
    {
        float4 d;
#pragma unroll
        for (int q = 0; q < 2; q++) { ld_a(0, q, d); st_a(0, q, d); }
#pragma unroll
        for (int q = 0; q < 4; q++) { ld_b(0, q, d); st_b(0, q, d); }
    }
    __syncthreads();

#pragma unroll 1
    for (int it = 0; it < NIT; it++) {
        const char* As = smem + (it & 1) * STAGE_B;
        const char* Bs = As + A_TILE_B;
        const int nst = (it + 1) & 1;
        const bool pf = (it + 1 < NIT);
        float4 s0, s1, s2, s3;

        // half1 prefetch: A records + first 2 B records
        if (pf) {
            ld_a(it + 1, 0, s0); ld_a(it + 1, 1, s1);
            ld_b(it + 1, 0, s2); ld_b(it + 1, 1, s3);
        }
        compute_s(As, Bs, 0);
        if (pf) {
            st_a(nst, 0, s0); st_a(nst, 1, s1);
            st_b(nst, 0, s2); st_b(nst, 1, s3);
            ld_b(it + 1, 2, s0); ld_b(it + 1, 3, s1);
        }
        compute_s(As, Bs, 1);
        if (pf) {
            st_b(nst, 2, s0); st_b(nst, 3, s1);
        }
        __syncthreads();
    }

    if (EPI == 0) {
#pragma unroll
        for (int mt = 0; mt < 4; mt++) {
            int gr = rowbase + wm * 64 + mt * 16 + g;
#pragma unroll
            for (int nt = 0; nt < 4; nt++) {
                int col = wn * 32 + nt * 8 + tq * 2;
                float b0v = __ldg(&bias[col]);
                float b1v = __ldg(&bias[col + 1]);
                if (gr < M) {
                    float2 v = make_float2(fmaxf(acc[mt][nt][0] + b0v, 0.f),
                                           fmaxf(acc[mt][nt][1] + b1v, 0.f));
                    *(float2*)(out + (size_t)gr * 256 + col) = v;
                }
                if (gr + 8 < M) {
                    float2 v = make_float2(fmaxf(acc[mt][nt][2] + b0v, 0.f),
                                           fmaxf(acc[mt][nt][3] + b1v, 0.f));
                    *(float2*)(out + (size_t)(gr + 8) * 256 + col) = v;
                }
            }
        }
    } else {
        // ---- half-stash epilogue ----
        // warps with wn>=4 hold pb (tile cols 128..255): stash to Sc[128][SCS]
        float* Sc = (float*)smem;                     // 128*SCS floats = 67584 B
        float* spart = (float*)(smem + 128 * SCS * 4); // [4][128]
        if (wn >= 4) {
#pragma unroll
            for (int mt = 0; mt < 4; mt++) {
                int lr = wm * 64 + mt * 16 + g;
#pragma unroll
                for (int nt = 0; nt < 4; nt++) {
                    int lc = (wn - 4) * 32 + nt * 8 + tq * 2;   // pb col 0..127
                    Sc[lr * SCS + lc]           = acc[mt][nt][0];
                    Sc[lr * SCS + lc + 1]       = acc[mt][nt][1];
                    Sc[(lr + 8) * SCS + lc]     = acc[mt][nt][2];
                    Sc[(lr + 8) * SCS + lc + 1] = acc[mt][nt][3];
                }
            }
        }
        __syncthreads();
        if (wn < 4) {
            // pa warps: products + per-row partial sums over this warp's 32 cols
#pragma unroll
            for (int mt = 0; mt < 4; mt++) {
                int r0 = wm * 64 + mt * 16 + g;
                float sum0 = 0.f, sum1 = 0.f;
#pragma unroll
                for (int nt = 0; nt < 4; nt++) {
                    int c = wn * 32 + nt * 8 + tq * 2;   // pa col 0..127
                    int gc = cb * 128 + c;
                    float ba0 = __ldg(&ba[gc]),   ba1 = __ldg(&ba[gc + 1]);
                    float bb0 = __ldg(&bb[gc]),   bb1 = __ldg(&bb[gc + 1]);
                    float wc0 = __ldg(&Wc[gc]),   wc1 = __ldg(&Wc[gc + 1]);
                    // row r0
                    {
                        float t0 = tanhf(acc[mt][nt][0] + ba0);
                        float s0v = 1.0f / (1.0f + __expf(-(Sc[r0 * SCS + c] + bb0)));
                        float t1 = tanhf(acc[mt][nt][1] + ba1);
                        float s1v = 1.0f / (1.0f + __expf(-(Sc[r0 * SCS + c + 1] + bb1)));
                        sum0 = fmaf(t0 * s0v, wc0, sum0);
                        sum0 = fmaf(t1 * s1v, wc1, sum0);
                    }
                    // row r0+8
                    {
                        float t0 = tanhf(acc[mt][nt][2] + ba0);
                        float s0v = 1.0f / (1.0f + __expf(-(Sc[(r0 + 8) * SCS + c] + bb0)));
                        float t1 = tanhf(acc[mt][nt][3] + ba1);
                        float s1v = 1.0f / (1.0f + __expf(-(Sc[(r0 + 8) * SCS + c + 1] + bb1)));
                        sum1 = fmaf(t0 * s0v, wc0, sum1);
                        sum1 = fmaf(t1 * s1v, wc1, sum1);
                    }
                }
                // quad reduce (lanes share g, tq=0..3)
                sum0 += __shfl_xor_sync(0xffffffffu, sum0, 1);
                sum0 += __shfl_xor_sync(0xffffffffu, sum0, 2);
                sum1 += __shfl_xor_sync(0xffffffffu, sum1, 1);
                sum1 += __shfl_xor_sync(0xffffffffu, sum1, 2);
                if (tq == 0) {
                    spart[wn * 128 + r0]     = sum0;
                    spart[wn * 128 + r0 + 8] = sum1;
                }
            }
        }
        __syncthreads();
        if (tid < 128) {
            float s = spart[tid] + spart[128 + tid] + spart[256 + tid] + spart[384 + tid];
            int gr = rowbase + tid;
            if (gr < M) out[(size_t)cb * MAXN + gr] = s;
        }
    }
}

// ============ fused pooling partials + per-block top/bottom-8 ==============
__global__ void pool_topk_partial(const float* __restrict__ x,
                                  const float* __restrict__ sp, int N,
                                  float* __restrict__ part, float* __restrict__ psum,
                                  float* __restrict__ cand_v, int* __restrict__ cand_i)
{
    __shared__ float ws[256];
    __shared__ float cv[256 * KS];
    __shared__ int   ci[256 * KS];
    __shared__ float rv[256];
    __shared__ int   rs[256];

    const int tid = threadIdx.x;
    int chunk = (N + gridDim.x - 1) / gridDim.x;
    int start = blockIdx.x * chunk;
    int end = min(start + chunk, N);

    float tv[KS], bv[KS];
    int ti[KS], bi[KS];
#pragma unroll
    for (int k = 0; k < KS; k++) { tv[k] = -FLT_MAX; ti[k] = 0; bv[k] = FLT_MAX; bi[k] = 0; }

    float accx = 0.f, wsum = 0.f;
    for (int t0 = start; t0 < end; t0 += 256) {
        int i = t0 + tid;
        float w = 0.f;
        if (i < end) {
            float s = load_score(sp, i);
            w = __expf(s);
            if (s > tv[KS - 1]) {
                tv[KS - 1] = s; ti[KS - 1] = i;
                for (int j = KS - 1; j > 0; j--) {
                    if (tv[j] > tv[j - 1]) {
                        float fv = tv[j]; tv[j] = tv[j - 1]; tv[j - 1] = fv;
                        int fi = ti[j]; ti[j] = ti[j - 1]; ti[j - 1] = fi;
                    } else break;
                }
            }
            if (s < bv[KS - 1]) {
                bv[KS - 1] = s; bi[KS - 1] = i;
                for (int j = KS - 1; j > 0; j--) {
                    if (bv[j] < bv[j - 1]) {
                        float fv = bv[j]; bv[j] = bv[j - 1]; bv[j - 1] = fv;
                        int fi = bi[j]; bi[j] = bi[j - 1]; bi[j - 1] = fi;
                    } else break;
                }
            }
        }
        ws[tid] = w;
        __syncthreads();
        int cnt = min(256, end - t0);
        for (int ii = 0; ii < cnt; ii++) {
            float w2 = ws[ii];
            accx = fmaf(w2, x[(size_t)(t0 + ii) * HID + tid], accx);
            wsum += w2;
        }
        __syncthreads();
    }
    part[blockIdx.x * HID + tid] = accx;
    if (tid == 0) psum[blockIdx.x] = wsum;

    // ---- block-level top 8 ----
#pragma unroll
    for (int k = 0; k < KS; k++) { cv[tid * KS + k] = tv[k]; ci[tid * KS + k] = ti[k]; }
    __syncthreads();
    for (int pass = 0; pass < KS; pass++) {
        float bestv = -FLT_MAX; int bestslot = tid * KS;
#pragma unroll
        for (int k = 0; k < KS; k++) {
            int sl = tid * KS + k;
            if (cv[sl] > bestv) { bestv = cv[sl]; bestslot = sl; }
        }
        rv[tid] = bestv; rs[tid] = bestslot;
        __syncthreads();
        for (int str = 128; str > 0; str >>= 1) {
            if (tid < str && rv[tid + str] > rv[tid]) { rv[tid] = rv[tid + str]; rs[tid] = rs[tid + str]; }
            __syncthreads();
        }
        if (tid == 0) {
            cand_v[blockIdx.x * 16 + pass] = rv[0];
            cand_i[blockIdx.x * 16 + pass] = ci[rs[0]];
            cv[rs[0]] = -FLT_MAX;
        }
        __syncthreads();
    }
    // ---- block-level bottom 8 ----
#pragma unroll
    for (int k = 0; k < KS; k++) { cv[tid * KS + k] = bv[k]; ci[tid * KS + k] = bi[k]; }
    __syncthreads();
    for (int pass = 0; pass < KS; pass++) {
        float bestv = FLT_MAX; int bestslot = tid * KS;
#pragma unroll
        for (int k = 0; k < KS; k++) {
            int sl = tid * KS + k;
            if (cv[sl] < bestv) { bestv = cv[sl]; bestslot = sl; }
        }
        rv[tid] = bestv; rs[tid] = bestslot;
        __syncthreads();
        for (int str = 128; str > 0; str >>= 1) {
            if (tid < str && rv[tid + str] < rv[tid]) { rv[tid] = rv[tid + str]; rs[tid] = rs[tid + str]; }
            __syncthreads();
        }
        if (tid == 0) {
            cand_v[blockIdx.x * 16 + KS + pass] = rv[0];
            cand_i[blockIdx.x * 16 + KS + pass] = ci[rs[0]];
            cv[rs[0]] = FLT_MAX;
        }
        __syncthreads();
    }
}

// ======= fused final: candidate merge + pool merge + losses + output =======
__global__ void final_fused(const float* __restrict__ cand_v, const int* __restrict__ cand_i,
                            const float* __restrict__ part, const float* __restrict__ psum,
                            const float* __restrict__ W_cls, const float* __restrict__ b_cls,
                            const float* __restrict__ W_inst, const float* __restrict__ b_inst,
                            const int* __restrict__ label_p, const float* __restrict__ xbuf,
                            float* __restrict__ out)
{
    __shared__ float cv[256 * KS];
    __shared__ int   ci[256 * KS];
    __shared__ float rv[256];
    __shared__ int   rs[256];
    __shared__ float Msh[HID];
    __shared__ float szs[256];
    __shared__ int   sel[2 * KS];
    const int tid = threadIdx.x;

    // ---- global top 8 (NB blocks; tid>=NB padded with sentinels) ----
#pragma unroll
    for (int k = 0; k < KS; k++) {
        cv[tid * KS + k] = (tid < NB) ? cand_v[tid * 16 + k] : -FLT_MAX;
        ci[tid * KS + k] = (tid < NB) ? cand_i[tid * 16 + k] : 0;
    }
    __syncthreads();
    for (int pass = 0; pass < KS; pass++) {
        float bestv = -FLT_MAX; int bestslot = tid * KS;
#pragma unroll
        for (int k = 0; k < KS; k++) {
            int sl = tid * KS + k;
            if (cv[sl] > bestv) { bestv = cv[sl]; bestslot = sl; }
        }
        rv[tid] = bestv; rs[tid] = bestslot;
        __syncthreads();
        for (int str = 128; str > 0; str >>= 1) {
            if (tid < str && rv[tid + str] > rv[tid]) { rv[tid] = rv[tid + str]; rs[tid] = rs[tid + str]; }
            __syncthreads();
        }
        if (tid == 0) { sel[pass] = ci[rs[0]]; cv[rs[0]] = -FLT_MAX; }
        __syncthreads();
    }
    // ---- global bottom 8 ----
#pragma unroll
    for (int k = 0; k < KS; k++) {
        cv[tid * KS + k] = (tid < NB) ? cand_v[tid * 16 + KS + k] : FLT_MAX;
        ci[tid * KS + k] = (tid < NB) ? cand_i[tid * 16 + KS + k] : 0;
    }
    __syncthreads();
    for (int pass = 0; pass < KS; pass++) {
        float bestv = FLT_MAX; int bestslot = tid * KS;
#pragma unroll
        for (int k = 0; k < KS; k++) {
            int sl = tid * KS + k;
            if (cv[sl] < bestv) { bestv = cv[sl]; bestslot = sl; }
        }
        rv[tid] = bestv; rs[tid] = bestslot;
        __syncthreads();
        for (int str = 128; str > 0; str >>= 1) {
            if (tid < str && rv[tid + str] < rv[tid]) { rv[tid] = rv[tid + str]; rs[tid] = rs[tid + str]; }
            __syncthreads();
        }
        if (tid == 0) { sel[KS + pass] = ci[rs[0]]; cv[rs[0]] = FLT_MAX; }
        __syncthreads();
    }

    // ---- pool merge ----
    float accm = 0.f;
    for (int b = 0; b < NB; b++) accm += part[b * HID + tid];
    szs[tid] = (tid < NB) ? psum[tid] : 0.f;
    __syncthreads();
    for (int str = 128; str > 0; str >>= 1) {
        if (tid < str) szs[tid] += szs[tid + str];
        __syncthreads();
    }
    Msh[tid] = accm / szs[0];
    __syncthreads();

    // ---- warp 0: instance SVM loss + bag classifier ----
    if (tid < 32) {
        int lane = tid;
        int label = label_p[0];
        float my = 0.0f;
        if (lane < 2 * KS) {
            int id = sel[lane];
            const float* xr = xbuf + (size_t)id * HID;
            const float* w0 = W_inst + (size_t)(label * 2 + 0) * HID;
            const float* w1 = W_inst + (size_t)(label * 2 + 1) * HID;
            float s0 = b_inst[label * 2 + 0], s1 = b_inst[label * 2 + 1];
            for (int j = 0; j < HID; j++) {
                float xv = xr[j];
                s0 = fmaf(xv, w0[j], s0);
                s1 = fmaf(xv, w1[j], s1);
            }
            int t = (lane < KS) ? 1 : 0;
            float a0 = s0 + ((t == 0) ? 0.0f : 1.0f);
            float a1 = s1 + ((t == 1) ? 0.0f : 1.0f);
            float mm = fmaxf(a0, a1);
            float lse = mm + logf(expf(a0 - mm) + expf(a1 - mm));
            float sy = (t == 1) ? s1 : s0;
            my = lse - sy;
        }
#pragma unroll
        for (int off = 16; off >= 1; off >>= 1)
            my += __shfl_xor_sync(0xffffffffu, my, off);

        if (lane == 0) {
            float loss = my / (float)(2 * KS);
            float l0 = b_cls[0], l1 = b_cls[1];
            for (int j = 0; j < HID; j++) {
                float m = Msh[j];
                l0 = fmaf(W_cls[j], m, l0);
                l1 = fmaf(W_cls[HID + j], m, l1);
            }
            float mm = fmaxf(l0, l1);
            float e0 = expf(l0 - mm), e1 = expf(l1 - mm);
            float Z = e0 + e1;
            out[0] = l0;
            out[1] = l1;
            out[2] = e0 / Z;
            out[3] = e1 / Z;
            out[4] = (l1 > l0) ? 1.0f : 0.0f;
            out[5] = loss;
        }
    }
}

// ---------------- launch ----------------
extern "C" void kernel_launch(void* const* d_in, const int* in_sizes, int n_in,
                              void* d_out, int out_size)
{
    const float* h     = (const float*)d_in[0];
    const int*   label = (const int*)d_in[1];
    const float* W_fc  = (const float*)d_in[2];
    const float* b_fc  = (const float*)d_in[3];
    const float* Wa    = (const float*)d_in[4];
    const float* ba    = (const float*)d_in[5];
    const float* Wb    = (const float*)d_in[6];
    const float* bb    = (const float*)d_in[7];
    const float* Wc    = (const float*)d_in[8];
    const float* bc    = (const float*)d_in[9];  // softmax-invariant; unused downstream
    const float* W_cls = (const float*)d_in[10];
    const float* b_cls = (const float*)d_in[11];
    const float* W_inst= (const float*)d_in[12];
    const float* b_inst= (const float*)d_in[13];
    (void)bc;

    int N = in_sizes[0] / FEAT;

    float *px, *pspart, *ppart, *ppsum, *pcv;
    int *pci;
    cudaGetSymbolAddress((void**)&px, g_x);
    cudaGetSymbolAddress((void**)&pspart, g_spart);
    cudaGetSymbolAddress((void**)&ppart, g_pool_part);
    cudaGetSymbolAddress((void**)&ppsum, g_psum);
    cudaGetSymbolAddress((void**)&pcv, g_cand_v);
    cudaGetSymbolAddress((void**)&pci, g_cand_i);

    int rbs = (N + 127) / 128;

    // K1: x = relu(h @ Wfc^T + b_fc); CTA 128x256, 512 threads
    cudaFuncSetAttribute(gemm_mma<0>, cudaFuncAttributeMaxDynamicSharedMemorySize, SMEM_TOT);
    gemm_mma<0><<<dim3(rbs, 1), 512, SMEM_TOT>>>(
        h, W_fc, nullptr, b_fc, nullptr, nullptr, nullptr, px, N, FEAT);

    // K2: partial attention scores; 2 col-blocks of 128 attention channels
    cudaFuncSetAttribute(gemm_mma<1>, cudaFuncAttributeMaxDynamicSharedMemorySize, SMEM_TOT);
    gemm_mma<1><<<dim3(rbs, 2), 512, SMEM_TOT>>>(
        px, Wa, Wb, nullptr, ba, bb, Wc, pspart, N, HID);

    // fused pooling partials + per-block top/bottom-8 candidates
    pool_topk_partial<<<NB, 256>>>(px, pspart, N, ppart, ppsum, pcv, pci);

    // fused final: merge candidates + pool + instance loss + bag classifier
    final_fused<<<1, 256>>>(pcv, pci, ppart, ppsum, W_cls, b_cls,
                            W_inst, b_inst, label, px, (float*)d_out);
}

// round 16
// speedup vs baseline: 3.0304x; 1.2495x over previous
#include <cuda_runtime.h>
#include <cuda_fp16.h>
#include <float.h>
#include <math.h>
#include <cstdint>

// ---------------- problem constants ----------------
#define FEAT 1024
#define HID 256
#define MAXN 100000
#define KS 8   // K_SAMPLE
#define NB 64  // pool/topk partial blocks

// ---------------- scratch (device globals; no allocation) ----------------
__device__ float g_x[(size_t)MAXN * HID];       // relu(h @ Wfc^T + b)
__device__ float g_spart[2 * (size_t)MAXN];     // partial attention scores (2 planes)
__device__ float g_pool_part[NB * HID];
__device__ float g_psum[NB];
__device__ float g_cand_v[NB * 16];             // per block: 8 top vals, 8 bottom vals
__device__ int   g_cand_i[NB * 16];

// ---------------- helpers ----------------
__device__ __forceinline__ uint32_t pack_f16(float v0, float v1) {
    __half2 p = __floats2half2_rn(v0, v1);
    return *reinterpret_cast<uint32_t*>(&p);
}

// m16n8k16 row.col fp16 MMA, fp32 accumulate (sm_80+, no 'a' features)
__device__ __forceinline__ void mma_f16(float* c, uint32_t a0, uint32_t a1,
                                        uint32_t a2, uint32_t a3,
                                        uint32_t b0, uint32_t b1) {
    asm volatile(
        "mma.sync.aligned.m16n8k16.row.col.f32.f16.f16.f32 "
        "{%0,%1,%2,%3}, {%4,%5,%6,%7}, {%8,%9}, {%0,%1,%2,%3};\n"
        : "+f"(c[0]), "+f"(c[1]), "+f"(c[2]), "+f"(c[3])
        : "r"(a0), "r"(a1), "r"(a2), "r"(a3), "r"(b0), "r"(b1));
}

__device__ __forceinline__ float load_score(const float* __restrict__ p, int i) {
    return p[i] + p[MAXN + i];
}

// ---- smem layout ----
// A and B both single fp16: 96B row stride (64B data): per k16-step s (32B),
// per t (8B): {v(pair p), v(pair p+4)}, p = 8s+t, pair = k/2.
// LDS.64 fragment phases: addr mod 128 = 96g + 8tq -> distinct across lanes.
#define RS_A 96
#define RS_B 96
#define A_ROWS 128
#define B_ROWS 256
#define A_TILE_B (A_ROWS * RS_A)             // 12288
#define B_TILE_B (B_ROWS * RS_B)             // 24576
#define STAGE_B  (A_TILE_B + B_TILE_B)       // 36864
#define SMEM_TOT (2 * STAGE_B)               // 73728
#define SCS 132                              // K2 epi pb-stash row stride (floats)

// ================= fp16 single-term mma.sync GEMM, 512 threads =============
// CTA tile 128 x 256, BK=32, 16 warps of 64x32, register-prefetch pipeline.
// C = A_fp16 @ B_fp16^T (both rounded once; rel err ~1e-4, threshold 1e-3)
// EPI=0: out[row*256+col] = relu(C + bias[col]); B rows r -> B0[r]
// EPI=1: cb=blockIdx.y; B rows: r<128 -> Wa[cb*128+r] (pa), else Wb[...] (pb)
//        epilogue: partial attn score over 128 channels -> out[cb*MAXN + row]
template <int EPI>
__global__ void __launch_bounds__(512)
gemm_mma(const float* __restrict__ A, const float* __restrict__ B0,
         const float* __restrict__ B1, const float* __restrict__ bias,
         const float* __restrict__ ba, const float* __restrict__ bb,
         const float* __restrict__ Wc,
         float* __restrict__ out, int M, int K)
{
    extern __shared__ __align__(16) char smem[];
    const int tid = threadIdx.x;
    const int lane = tid & 31;
    const int wid = tid >> 5;
    const int wm = wid & 1;         // 2 row-slices of 64
    const int wn = wid >> 1;        // 8 col-slices of 32
    const int g = lane >> 2;        // 0..7
    const int tq = lane & 3;        // 0..3
    const int cb = (EPI == 1) ? blockIdx.y : 0;
    const int rowbase = blockIdx.x * 128;
    const int NIT = K >> 5;
    const int rr = tid >> 3;        // record row within 64-batch (0..63)
    const int ss = (tid >> 2) & 1;
    const int tt = tid & 3;

    float acc[4][4][4];
#pragma unroll
    for (int mt = 0; mt < 4; mt++)
#pragma unroll
        for (int nt = 0; nt < 4; nt++)
#pragma unroll
            for (int j = 0; j < 4; j++) acc[mt][nt][j] = 0.f;

    auto ld_a = [&](int it, int q, float4& d) {        // q: 0..1 (64 rows each)
        int kf = (it << 5) + 16 * ss + 2 * tt;
        int r = q * 64 + rr;
        int grow = rowbase + r;
        if (grow < M) {
            const float* src = A + (size_t)grow * K + kf;
            float2 u = *(const float2*)(src);
            float2 v = *(const float2*)(src + 8);
            d = make_float4(u.x, u.y, v.x, v.y);
        } else d = make_float4(0.f, 0.f, 0.f, 0.f);
    };
    auto ld_b = [&](int it, int q, float4& d) {        // q: 0..3 (64 rows each)
        int kf = (it << 5) + 16 * ss + 2 * tt;
        int r = q * 64 + rr;
        const float* brow;
        if (EPI == 0) brow = B0 + (size_t)r * K;
        else { int c = cb * 128 + (r & 127); brow = ((r < 128) ? B0 : B1) + (size_t)c * K; }
        float2 u = *(const float2*)(brow + kf);
        float2 v = *(const float2*)(brow + kf + 8);
        d = make_float4(u.x, u.y, v.x, v.y);
    };
    auto st_a = [&](int stage, int q, const float4& d) {
        char* As = smem + stage * STAGE_B;
        int r = q * 64 + rr;
        uint32_t p0 = pack_f16(d.x, d.y);
        uint32_t p1 = pack_f16(d.z, d.w);
        *(uint2*)(As + r * RS_A + ss * 32 + tt * 8) = make_uint2(p0, p1);
    };
    auto st_b = [&](int stage, int q, const float4& d) {
        char* Bs = smem + stage * STAGE_B + A_TILE_B;
        int r = q * 64 + rr;
        uint32_t p0 = pack_f16(d.x, d.y);
        uint32_t p1 = pack_f16(d.z, d.w);
        *(uint2*)(Bs + r * RS_B + ss * 32 + tt * 8) = make_uint2(p0, p1);
    };
    auto compute_s = [&](const char* As, const char* Bs, int s) {
        uint2 af[4][2];
#pragma unroll
        for (int mt = 0; mt < 4; mt++) {
            int r0 = wm * 64 + mt * 16 + g;
            af[mt][0] = *(const uint2*)(As + r0 * RS_A + s * 32 + tq * 8);
            af[mt][1] = *(const uint2*)(As + (r0 + 8) * RS_A + s * 32 + tq * 8);
        }
#pragma unroll
        for (int nt = 0; nt < 4; nt++) {
            int nr = wn * 32 + nt * 8 + g;
            uint2 bf = *(const uint2*)(Bs + nr * RS_B + s * 32 + tq * 8);
#pragma unroll
            for (int mt = 0; mt < 4; mt++) {
                mma_f16(acc[mt][nt], af[mt][0].x, af[mt][1].x, af[mt][0].y, af[mt][1].y, bf.x, bf.y);
            }
        }
    };

    // prologue: stage 0
    {
        float4 d;
#pragma unroll
        for (int q = 0; q < 2; q++) { ld_a(0, q, d); st_a(0, q, d); }
#pragma unroll
        for (int q = 0; q < 4; q++) { ld_b(0, q, d); st_b(0, q, d); }
    }
    __syncthreads();

#pragma unroll 1
    for (int it = 0; it < NIT; it++) {
        const char* As = smem + (it & 1) * STAGE_B;
        const char* Bs = As + A_TILE_B;
        const int nst = (it + 1) & 1;
        const bool pf = (it + 1 < NIT);
        float4 s0, s1, s2, s3;

        // half1 prefetch: A records + first 2 B records
        if (pf) {
            ld_a(it + 1, 0, s0); ld_a(it + 1, 1, s1);
            ld_b(it + 1, 0, s2); ld_b(it + 1, 1, s3);
        }
        compute_s(As, Bs, 0);
        if (pf) {
            st_a(nst, 0, s0); st_a(nst, 1, s1);
            st_b(nst, 0, s2); st_b(nst, 1, s3);
            ld_b(it + 1, 2, s0); ld_b(it + 1, 3, s1);
        }
        compute_s(As, Bs, 1);
        if (pf) {
            st_b(nst, 2, s0); st_b(nst, 3, s1);
        }
        __syncthreads();
    }

    if (EPI == 0) {
#pragma unroll
        for (int mt = 0; mt < 4; mt++) {
            int gr = rowbase + wm * 64 + mt * 16 + g;
#pragma unroll
            for (int nt = 0; nt < 4; nt++) {
                int col = wn * 32 + nt * 8 + tq * 2;
                float b0v = __ldg(&bias[col]);
                float b1v = __ldg(&bias[col + 1]);
                if (gr < M) {
                    float2 v = make_float2(fmaxf(acc[mt][nt][0] + b0v, 0.f),
                                           fmaxf(acc[mt][nt][1] + b1v, 0.f));
                    *(float2*)(out + (size_t)gr * 256 + col) = v;
                }
                if (gr + 8 < M) {
                    float2 v = make_float2(fmaxf(acc[mt][nt][2] + b0v, 0.f),
                                           fmaxf(acc[mt][nt][3] + b1v, 0.f));
                    *(float2*)(out + (size_t)(gr + 8) * 256 + col) = v;
                }
            }
        }
    } else {
        // ---- half-stash epilogue ----
        // warps with wn>=4 hold pb (tile cols 128..255): stash to Sc[128][SCS]
        float* Sc = (float*)smem;                      // 128*SCS floats = 67584 B
        float* spart = (float*)(smem + 128 * SCS * 4); // [4][128] = 2048 B
        if (wn >= 4) {
#pragma unroll
            for (int mt = 0; mt < 4; mt++) {
                int lr = wm * 64 + mt * 16 + g;
#pragma unroll
                for (int nt = 0; nt < 4; nt++) {
                    int lc = (wn - 4) * 32 + nt * 8 + tq * 2;   // pb col 0..127
                    Sc[lr * SCS + lc]           = acc[mt][nt][0];
                    Sc[lr * SCS + lc + 1]       = acc[mt][nt][1];
                    Sc[(lr + 8) * SCS + lc]     = acc[mt][nt][2];
                    Sc[(lr + 8) * SCS + lc + 1] = acc[mt][nt][3];
                }
            }
        }
        __syncthreads();
        if (wn < 4) {
#pragma unroll
            for (int mt = 0; mt < 4; mt++) {
                int r0 = wm * 64 + mt * 16 + g;
                float sum0 = 0.f, sum1 = 0.f;
#pragma unroll
                for (int nt = 0; nt < 4; nt++) {
                    int c = wn * 32 + nt * 8 + tq * 2;   // pa col 0..127
                    int gc = cb * 128 + c;
                    float ba0 = __ldg(&ba[gc]),   ba1 = __ldg(&ba[gc + 1]);
                    float bb0 = __ldg(&bb[gc]),   bb1 = __ldg(&bb[gc + 1]);
                    float wc0 = __ldg(&Wc[gc]),   wc1 = __ldg(&Wc[gc + 1]);
                    {
                        float t0 = tanhf(acc[mt][nt][0] + ba0);
                        float s0v = 1.0f / (1.0f + __expf(-(Sc[r0 * SCS + c] + bb0)));
                        float t1 = tanhf(acc[mt][nt][1] + ba1);
                        float s1v = 1.0f / (1.0f + __expf(-(Sc[r0 * SCS + c + 1] + bb1)));
                        sum0 = fmaf(t0 * s0v, wc0, sum0);
                        sum0 = fmaf(t1 * s1v, wc1, sum0);
                    }
                    {
                        float t0 = tanhf(acc[mt][nt][2] + ba0);
                        float s0v = 1.0f / (1.0f + __expf(-(Sc[(r0 + 8) * SCS + c] + bb0)));
                        float t1 = tanhf(acc[mt][nt][3] + ba1);
                        float s1v = 1.0f / (1.0f + __expf(-(Sc[(r0 + 8) * SCS + c + 1] + bb1)));
                        sum1 = fmaf(t0 * s0v, wc0, sum1);
                        sum1 = fmaf(t1 * s1v, wc1, sum1);
                    }
                }
                sum0 += __shfl_xor_sync(0xffffffffu, sum0, 1);
                sum0 += __shfl_xor_sync(0xffffffffu, sum0, 2);
                sum1 += __shfl_xor_sync(0xffffffffu, sum1, 1);
                sum1 += __shfl_xor_sync(0xffffffffu, sum1, 2);
                if (tq == 0) {
                    spart[wn * 128 + r0]     = sum0;
                    spart[wn * 128 + r0 + 8] = sum1;
                }
            }
        }
        __syncthreads();
        if (tid < 128) {
            float s = spart[tid] + spart[128 + tid] + spart[256 + tid] + spart[384 + tid];
            int gr = rowbase + tid;
            if (gr < M) out[(size_t)cb * MAXN + gr] = s;
        }
    }
}

// ============ fused pooling partials + per-block top/bottom-8 ==============
__global__ void pool_topk_partial(const float* __restrict__ x,
                                  const float* __restrict__ sp, int N,
                                  float* __restrict__ part, float* __restrict__ psum,
                                  float* __restrict__ cand_v, int* __restrict__ cand_i)
{
    __shared__ float ws[256];
    __shared__ float cv[256 * KS];
    __shared__ int   ci[256 * KS];
    __shared__ float rv[256];
    __shared__ int   rs[256];

    const int tid = threadIdx.x;
    int chunk = (N + gridDim.x - 1) / gridDim.x;
    int start = blockIdx.x * chunk;
    int end = min(start + chunk, N);

    float tv[KS], bv[KS];
    int ti[KS], bi[KS];
#pragma unroll
    for (int k = 0; k < KS; k++) { tv[k] = -FLT_MAX; ti[k] = 0; bv[k] = FLT_MAX; bi[k] = 0; }

    float accx = 0.f, wsum = 0.f;
    for (int t0 = start; t0 < end; t0 += 256) {
        int i = t0 + tid;
        float w = 0.f;
        if (i < end) {
            float s = load_score(sp, i);
            w = __expf(s);
            if (s > tv[KS - 1]) {
                tv[KS - 1] = s; ti[KS - 1] = i;
                for (int j = KS - 1; j > 0; j--) {
                    if (tv[j] > tv[j - 1]) {
                        float fv = tv[j]; tv[j] = tv[j - 1]; tv[j - 1] = fv;
                        int fi = ti[j]; ti[j] = ti[j - 1]; ti[j - 1] = fi;
                    } else break;
                }
            }
            if (s < bv[KS - 1]) {
                bv[KS - 1] = s; bi[KS - 1] = i;
                for (int j = KS - 1; j > 0; j--) {
                    if (bv[j] < bv[j - 1]) {
                        float fv = bv[j]; bv[j] = bv[j - 1]; bv[j - 1] = fv;
                        int fi = bi[j]; bi[j] = bi[j - 1]; bi[j - 1] = fi;
                    } else break;
                }
            }
        }
        ws[tid] = w;
        __syncthreads();
        int cnt = min(256, end - t0);
        for (int ii = 0; ii < cnt; ii++) {
            float w2 = ws[ii];
            accx = fmaf(w2, x[(size_t)(t0 + ii) * HID + tid], accx);
            wsum += w2;
        }
        __syncthreads();
    }
    part[blockIdx.x * HID + tid] = accx;
    if (tid == 0) psum[blockIdx.x] = wsum;

    // ---- block-level top 8 ----
#pragma unroll
    for (int k = 0; k < KS; k++) { cv[tid * KS + k] = tv[k]; ci[tid * KS + k] = ti[k]; }
    __syncthreads();
    for (int pass = 0; pass < KS; pass++) {
        float bestv = -FLT_MAX; int bestslot = tid * KS;
#pragma unroll
        for (int k = 0; k < KS; k++) {
            int sl = tid * KS + k;
            if (cv[sl] > bestv) { bestv = cv[sl]; bestslot = sl; }
        }
        rv[tid] = bestv; rs[tid] = bestslot;
        __syncthreads();
        for (int str = 128; str > 0; str >>= 1) {
            if (tid < str && rv[tid + str] > rv[tid]) { rv[tid] = rv[tid + str]; rs[tid] = rs[tid + str]; }
            __syncthreads();
        }
        if (tid == 0) {
            cand_v[blockIdx.x * 16 + pass] = rv[0];
            cand_i[blockIdx.x * 16 + pass] = ci[rs[0]];
            cv[rs[0]] = -FLT_MAX;
        }
        __syncthreads();
    }
    // ---- block-level bottom 8 ----
#pragma unroll
    for (int k = 0; k < KS; k++) { cv[tid * KS + k] = bv[k]; ci[tid * KS + k] = bi[k]; }
    __syncthreads();
    for (int pass = 0; pass < KS; pass++) {
        float bestv = FLT_MAX; int bestslot = tid * KS;
#pragma unroll
        for (int k = 0; k < KS; k++) {
            int sl = tid * KS + k;
            if (cv[sl] < bestv) { bestv = cv[sl]; bestslot = sl; }
        }
        rv[tid] = bestv; rs[tid] = bestslot;
        __syncthreads();
        for (int str = 128; str > 0; str >>= 1) {
            if (tid < str && rv[tid + str] < rv[tid]) { rv[tid] = rv[tid + str]; rs[tid] = rs[tid + str]; }
            __syncthreads();
        }
        if (tid == 0) {
            cand_v[blockIdx.x * 16 + KS + pass] = rv[0];
            cand_i[blockIdx.x * 16 + KS + pass] = ci[rs[0]];
            cv[rs[0]] = FLT_MAX;
        }
        __syncthreads();
    }
}

// ======= fused final: candidate merge + pool merge + losses + output =======
__global__ void final_fused(const float* __restrict__ cand_v, const int* __restrict__ cand_i,
                            const float* __restrict__ part, const float* __restrict__ psum,
                            const float* __restrict__ W_cls, const float* __restrict__ b_cls,
                            const float* __restrict__ W_inst, const float* __restrict__ b_inst,
                            const int* __restrict__ label_p, const float* __restrict__ xbuf,
                            float* __restrict__ out)
{
    __shared__ float cv[256 * KS];
    __shared__ int   ci[256 * KS];
    __shared__ float rv[256];
    __shared__ int   rs[256];
    __shared__ float Msh[HID];
    __shared__ float szs[256];
    __shared__ int   sel[2 * KS];
    const int tid = threadIdx.x;

    // ---- global top 8 (NB blocks; tid>=NB padded with sentinels) ----
#pragma unroll
    for (int k = 0; k < KS; k++) {
        cv[tid * KS + k] = (tid < NB) ? cand_v[tid * 16 + k] : -FLT_MAX;
        ci[tid * KS + k] = (tid < NB) ? cand_i[tid * 16 + k] : 0;
    }
    __syncthreads();
    for (int pass = 0; pass < KS; pass++) {
        float bestv = -FLT_MAX; int bestslot = tid * KS;
#pragma unroll
        for (int k = 0; k < KS; k++) {
            int sl = tid * KS + k;
            if (cv[sl] > bestv) { bestv = cv[sl]; bestslot = sl; }
        }
        rv[tid] = bestv; rs[tid] = bestslot;
        __syncthreads();
        for (int str = 128; str > 0; str >>= 1) {
            if (tid < str && rv[tid + str] > rv[tid]) { rv[tid] = rv[tid + str]; rs[tid] = rs[tid + str]; }
            __syncthreads();
        }
        if (tid == 0) { sel[pass] = ci[rs[0]]; cv[rs[0]] = -FLT_MAX; }
        __syncthreads();
    }
    // ---- global bottom 8 ----
#pragma unroll
    for (int k = 0; k < KS; k++) {
        cv[tid * KS + k] = (tid < NB) ? cand_v[tid * 16 + KS + k] : FLT_MAX;
        ci[tid * KS + k] = (tid < NB) ? cand_i[tid * 16 + KS + k] : 0;
    }
    __syncthreads();
    for (int pass = 0; pass < KS; pass++) {
        float bestv = FLT_MAX; int bestslot = tid * KS;
#pragma unroll
        for (int k = 0; k < KS; k++) {
            int sl = tid * KS + k;
            if (cv[sl] < bestv) { bestv = cv[sl]; bestslot = sl; }
        }
        rv[tid] = bestv; rs[tid] = bestslot;
        __syncthreads();
        for (int str = 128; str > 0; str >>= 1) {
            if (tid < str && rv[tid + str] < rv[tid]) { rv[tid] = rv[tid + str]; rs[tid] = rs[tid + str]; }
            __syncthreads();
        }
        if (tid == 0) { sel[KS + pass] = ci[rs[0]]; cv[rs[0]] = FLT_MAX; }
        __syncthreads();
    }

    // ---- pool merge ----
    float accm = 0.f;
    for (int b = 0; b < NB; b++) accm += part[b * HID + tid];
    szs[tid] = (tid < NB) ? psum[tid] : 0.f;
    __syncthreads();
    for (int str = 128; str > 0; str >>= 1) {
        if (tid < str) szs[tid] += szs[tid + str];
        __syncthreads();
    }
    Msh[tid] = accm / szs[0];
    __syncthreads();

    // ---- warp 0: instance SVM loss + bag classifier ----
    if (tid < 32) {
        int lane = tid;
        int label = label_p[0];
        float my = 0.0f;
        if (lane < 2 * KS) {
            int id = sel[lane];
            const float* xr = xbuf + (size_t)id * HID;
            const float* w0 = W_inst + (size_t)(label * 2 + 0) * HID;
            const float* w1 = W_inst + (size_t)(label * 2 + 1) * HID;
            float s0 = b_inst[label * 2 + 0], s1 = b_inst[label * 2 + 1];
            for (int j = 0; j < HID; j++) {
                float xv = xr[j];
                s0 = fmaf(xv, w0[j], s0);
                s1 = fmaf(xv, w1[j], s1);
            }
            int t = (lane < KS) ? 1 : 0;
            float a0 = s0 + ((t == 0) ? 0.0f : 1.0f);
            float a1 = s1 + ((t == 1) ? 0.0f : 1.0f);
            float mm = fmaxf(a0, a1);
            float lse = mm + logf(expf(a0 - mm) + expf(a1 - mm));
            float sy = (t == 1) ? s1 : s0;
            my = lse - sy;
        }
#pragma unroll
        for (int off = 16; off >= 1; off >>= 1)
            my += __shfl_xor_sync(0xffffffffu, my, off);

        if (lane == 0) {
            float loss = my / (float)(2 * KS);
            float l0 = b_cls[0], l1 = b_cls[1];
            for (int j = 0; j < HID; j++) {
                float m = Msh[j];
                l0 = fmaf(W_cls[j], m, l0);
                l1 = fmaf(W_cls[HID + j], m, l1);
            }
            float mm = fmaxf(l0, l1);
            float e0 = expf(l0 - mm), e1 = expf(l1 - mm);
            float Z = e0 + e1;
            out[0] = l0;
            out[1] = l1;
            out[2] = e0 / Z;
            out[3] = e1 / Z;
            out[4] = (l1 > l0) ? 1.0f : 0.0f;
            out[5] = loss;
        }
    }
}

// ---------------- launch ----------------
extern "C" void kernel_launch(void* const* d_in, const int* in_sizes, int n_in,
                              void* d_out, int out_size)
{
    const float* h     = (const float*)d_in[0];
    const int*   label = (const int*)d_in[1];
    const float* W_fc  = (const float*)d_in[2];
    const float* b_fc  = (const float*)d_in[3];
    const float* Wa    = (const float*)d_in[4];
    const float* ba    = (const float*)d_in[5];
    const float* Wb    = (const float*)d_in[6];
    const float* bb    = (const float*)d_in[7];
    const float* Wc    = (const float*)d_in[8];
    const float* bc    = (const float*)d_in[9];  // softmax-invariant; unused downstream
    const float* W_cls = (const float*)d_in[10];
    const float* b_cls = (const float*)d_in[11];
    const float* W_inst= (const float*)d_in[12];
    const float* b_inst= (const float*)d_in[13];
    (void)bc;

    int N = in_sizes[0] / FEAT;

    float *px, *pspart, *ppart, *ppsum, *pcv;
    int *pci;
    cudaGetSymbolAddress((void**)&px, g_x);
    cudaGetSymbolAddress((void**)&pspart, g_spart);
    cudaGetSymbolAddress((void**)&ppart, g_pool_part);
    cudaGetSymbolAddress((void**)&ppsum, g_psum);
    cudaGetSymbolAddress((void**)&pcv, g_cand_v);
    cudaGetSymbolAddress((void**)&pci, g_cand_i);

    int rbs = (N + 127) / 128;

    // K1: x = relu(h @ Wfc^T + b_fc); CTA 128x256, 512 threads
    cudaFuncSetAttribute(gemm_mma<0>, cudaFuncAttributeMaxDynamicSharedMemorySize, SMEM_TOT);
    gemm_mma<0><<<dim3(rbs, 1), 512, SMEM_TOT>>>(
        h, W_fc, nullptr, b_fc, nullptr, nullptr, nullptr, px, N, FEAT);

    // K2: partial attention scores; 2 col-blocks of 128 attention channels
    // EPI scratch = 128*SCS*4 + 2048 = 69632 <= SMEM_TOT
    cudaFuncSetAttribute(gemm_mma<1>, cudaFuncAttributeMaxDynamicSharedMemorySize, SMEM_TOT);
    gemm_mma<1><<<dim3(rbs, 2), 512, SMEM_TOT>>>(
        px, Wa, Wb, nullptr, ba, bb, Wc, pspart, N, HID);

    // fused pooling partials + per-block top/bottom-8 candidates
    pool_topk_partial<<<NB, 256>>>(px, pspart, N, ppart, ppsum, pcv, pci);

    // fused final: merge candidates + pool + instance loss + bag classifier
    final_fused<<<1, 256>>>(pcv, pci, ppart, ppsum, W_cls, b_cls,
                            W_inst, b_inst, label, px, (float*)d_out);
}